// round 9
// baseline (speedup 1.0000x reference)
#include <cuda_runtime.h>
#include <cuda_bf16.h>
#include <cstdint>
#include <math.h>

#define SEQ     4096
#define HID     2048
#define NHEADS  16
#define HDIM    128
#define NGLOB   16
#define HALFWIN 256
#define SCALE   0.08838834764831845f   // 128^-0.5

// ---------------- scratch (static device arrays) ----------------
__device__ __nv_bfloat16 g_Xh[SEQ * HID], g_Xl[SEQ * HID];
__device__ __nv_bfloat16 g_Qh[SEQ * HID], g_Ql[SEQ * HID];
__device__ __nv_bfloat16 g_Kh[SEQ * HID], g_Kl[SEQ * HID];
__device__ __nv_bfloat16 g_Vh[SEQ * HID], g_Vl[SEQ * HID];
__device__ __nv_bfloat16 g_Oh[SEQ * HID], g_Ol[SEQ * HID];
__device__ __nv_bfloat16 g_Wqh[HID * HID], g_Wql[HID * HID];
__device__ __nv_bfloat16 g_Wkh[HID * HID], g_Wkl[HID * HID];
__device__ __nv_bfloat16 g_Wvh[HID * HID], g_Wvl[HID * HID];
__device__ __nv_bfloat16 g_Woh[HID * HID], g_Wol[HID * HID];

// ---------------- asm helpers (compute_103-legal) ----------------
__device__ __forceinline__ uint32_t smem_u32(const void* p) {
    uint32_t a;
    asm("{ .reg .u64 t; cvta.to.shared.u64 t, %1; cvt.u32.u64 %0, t; }" : "=r"(a) : "l"(p));
    return a;
}
__device__ __forceinline__ void ldsm_x4(uint32_t& r0, uint32_t& r1, uint32_t& r2,
                                        uint32_t& r3, uint32_t addr) {
    asm volatile("ldmatrix.sync.aligned.m8n8.x4.shared.b16 {%0,%1,%2,%3}, [%4];"
                 : "=r"(r0), "=r"(r1), "=r"(r2), "=r"(r3) : "r"(addr));
}
__device__ __forceinline__ void ldsm_x2(uint32_t& r0, uint32_t& r1, uint32_t addr) {
    asm volatile("ldmatrix.sync.aligned.m8n8.x2.shared.b16 {%0,%1}, [%2];"
                 : "=r"(r0), "=r"(r1) : "r"(addr));
}
__device__ __forceinline__ void ldsm_x2t(uint32_t& r0, uint32_t& r1, uint32_t addr) {
    asm volatile("ldmatrix.sync.aligned.m8n8.x2.trans.shared.b16 {%0,%1}, [%2];"
                 : "=r"(r0), "=r"(r1) : "r"(addr));
}
__device__ __forceinline__ void mma_bf16(float* c, const uint32_t* a, const uint32_t* b) {
    asm volatile(
        "mma.sync.aligned.m16n8k16.row.col.f32.bf16.bf16.f32 "
        "{%0,%1,%2,%3}, {%4,%5,%6,%7}, {%8,%9}, {%0,%1,%2,%3};"
        : "+f"(c[0]), "+f"(c[1]), "+f"(c[2]), "+f"(c[3])
        : "r"(a[0]), "r"(a[1]), "r"(a[2]), "r"(a[3]), "r"(b[0]), "r"(b[1]));
}
__device__ __forceinline__ void cp_async16(uint32_t saddr, const void* g) {
    asm volatile("cp.async.cg.shared.global [%0], [%1], 16;" :: "r"(saddr), "l"(g));
}
#define CP_COMMIT() asm volatile("cp.async.commit_group;" ::: "memory")
#define CP_WAIT0()  asm volatile("cp.async.wait_group 0;" ::: "memory")
#define CP_WAIT1()  asm volatile("cp.async.wait_group 1;" ::: "memory")

__device__ __forceinline__ uint32_t pk2(__nv_bfloat16 a, __nv_bfloat16 b) {
    __nv_bfloat162 t = __halves2bfloat162(a, b);   // a -> low half
    return *(uint32_t*)&t;
}

// ---------------- conversion kernels ----------------
__global__ __launch_bounds__(256) void split_kernel(
    const float* __restrict__ x, __nv_bfloat16* __restrict__ h,
    __nv_bfloat16* __restrict__ l, int n4)
{
    int i = blockIdx.x * blockDim.x + threadIdx.x;
    if (i >= n4) return;
    float4 v = ((const float4*)x)[i];
    __nv_bfloat16 h0 = __float2bfloat16(v.x);
    __nv_bfloat16 h1 = __float2bfloat16(v.y);
    __nv_bfloat16 h2 = __float2bfloat16(v.z);
    __nv_bfloat16 h3 = __float2bfloat16(v.w);
    __nv_bfloat16 l0 = __float2bfloat16(v.x - __bfloat162float(h0));
    __nv_bfloat16 l1 = __float2bfloat16(v.y - __bfloat162float(h1));
    __nv_bfloat16 l2 = __float2bfloat16(v.z - __bfloat162float(h2));
    __nv_bfloat16 l3 = __float2bfloat16(v.w - __bfloat162float(h3));
    ((__nv_bfloat162*)h)[2 * i]     = __halves2bfloat162(h0, h1);
    ((__nv_bfloat162*)h)[2 * i + 1] = __halves2bfloat162(h2, h3);
    ((__nv_bfloat162*)l)[2 * i]     = __halves2bfloat162(l0, l1);
    ((__nv_bfloat162*)l)[2 * i + 1] = __halves2bfloat162(l2, l3);
}

// 4 weight transposes in one launch: blockIdx.z selects the matrix.
__global__ __launch_bounds__(256) void tsplit4_kernel(
    const float* __restrict__ W0, const float* __restrict__ W1,
    const float* __restrict__ W2, const float* __restrict__ W3,
    __nv_bfloat16* __restrict__ T0h, __nv_bfloat16* __restrict__ T0l,
    __nv_bfloat16* __restrict__ T1h, __nv_bfloat16* __restrict__ T1l,
    __nv_bfloat16* __restrict__ T2h, __nv_bfloat16* __restrict__ T2l,
    __nv_bfloat16* __restrict__ T3h, __nv_bfloat16* __restrict__ T3l)
{
    const float* W;
    __nv_bfloat16 *Th, *Tl;
    switch (blockIdx.z) {
        case 0: W = W0; Th = T0h; Tl = T0l; break;
        case 1: W = W1; Th = T1h; Tl = T1l; break;
        case 2: W = W2; Th = T2h; Tl = T2l; break;
        default: W = W3; Th = T3h; Tl = T3l; break;
    }
    __shared__ float t[32][33];
    int tx = threadIdx.x, ty = threadIdx.y;
    int bx = blockIdx.x * 32;   // N
    int by = blockIdx.y * 32;   // K
#pragma unroll
    for (int j = 0; j < 32; j += 8)
        t[ty + j][tx] = W[(size_t)(by + ty + j) * HID + bx + tx];
    __syncthreads();
#pragma unroll
    for (int j = 0; j < 32; j += 8) {
        float v = t[tx][ty + j];
        __nv_bfloat16 hb = __float2bfloat16(v);
        float lo = v - __bfloat162float(hb);
        size_t o = (size_t)(bx + ty + j) * HID + by + tx;
        Th[o] = hb;
        Tl[o] = __float2bfloat16(lo);
    }
}

// ---------------- HMMA bf16-split GEMM, 3-stage cp.async ----------------
// C = alpha * (Ah+Al)[M,K] @ (Bh+Bl)^T  (Bt stored [N][K] K-major)
// CTA 128x128, BK=32, 8 warps 2x4, warp tile 64x32, one barrier per chunk.
#define BK 32
#define SSTRIDE 40                         // elems per smem row (80 B)
#define TILE_ELEMS (128 * SSTRIDE)
#define TILE_BYTES (TILE_ELEMS * 2)        // 10240
#define STAGE_BYTES (4 * TILE_BYTES)       // 40960
#define GEMM_SMEM  (3 * STAGE_BYTES)       // 122880

__global__ __launch_bounds__(256) void gemm_mma(
    const __nv_bfloat16* __restrict__ Ah, const __nv_bfloat16* __restrict__ Al,
    const __nv_bfloat16* __restrict__ Bth, const __nv_bfloat16* __restrict__ Btl,
    float* __restrict__ Cf, __nv_bfloat16* __restrict__ Ch, __nv_bfloat16* __restrict__ Cl,
    int M, int N, int K, float alpha, int split_out)
{
    extern __shared__ char dsm[];
    const uint32_t sb = smem_u32(dsm);
    const int tid = threadIdx.x;
    const int wid = tid >> 5;
    const int lid = tid & 31;
    const int row0 = blockIdx.y * 128;
    const int col0 = blockIdx.x * 128;

    const int lr = tid >> 1;
    const int lhalf = (tid & 1) * 16;
    const __nv_bfloat16* gp0 = Ah  + (size_t)(row0 + lr) * K + lhalf;
    const __nv_bfloat16* gp1 = Al  + (size_t)(row0 + lr) * K + lhalf;
    const __nv_bfloat16* gp2 = Bth + (size_t)(col0 + lr) * K + lhalf;
    const __nv_bfloat16* gp3 = Btl + (size_t)(col0 + lr) * K + lhalf;
    const uint32_t soffB = (uint32_t)(lr * SSTRIDE + lhalf) * 2;

    const int warpM = (wid >> 2) * 64;
    const int warpN = (wid & 3) * 32;
    const int aRow = warpM + (lid & 15);
    const int aCol = (lid >> 4) * 8;
    const int bRow = warpN + (lid & 7);
    const int bCol = ((lid >> 3) & 1) * 8;

    float acc[4][4][4];
#pragma unroll
    for (int i = 0; i < 4; i++)
#pragma unroll
        for (int j = 0; j < 4; j++)
#pragma unroll
            for (int k = 0; k < 4; k++) acc[i][j][k] = 0.f;

    auto prefetch = [&](int c, int st) {
        uint32_t base = sb + st * STAGE_BYTES + soffB;
        const __nv_bfloat16* g0 = gp0 + c * BK;
        const __nv_bfloat16* g1 = gp1 + c * BK;
        const __nv_bfloat16* g2 = gp2 + c * BK;
        const __nv_bfloat16* g3 = gp3 + c * BK;
        cp_async16(base,                  g0); cp_async16(base + 16,                  g0 + 8);
        cp_async16(base + TILE_BYTES,     g1); cp_async16(base + TILE_BYTES + 16,     g1 + 8);
        cp_async16(base + 2 * TILE_BYTES, g2); cp_async16(base + 2 * TILE_BYTES + 16, g2 + 8);
        cp_async16(base + 3 * TILE_BYTES, g3); cp_async16(base + 3 * TILE_BYTES + 16, g3 + 8);
    };

    prefetch(0, 0); CP_COMMIT();
    prefetch(1, 1); CP_COMMIT();

    const int nch = K / BK;
    for (int c = 0; c < nch; c++) {
        if (c == nch - 1) { CP_WAIT0(); } else { CP_WAIT1(); }
        __syncthreads();
        if (c + 2 < nch) {
            prefetch(c + 2, (c + 2) % 3);
            CP_COMMIT();
        }

        const uint32_t st  = sb + (c % 3) * STAGE_BYTES;
        const uint32_t sAh = st;
        const uint32_t sAl = st + TILE_BYTES;
        const uint32_t sBh = st + 2 * TILE_BYTES;
        const uint32_t sBl = st + 3 * TILE_BYTES;

#pragma unroll
        for (int ks = 0; ks < 2; ks++) {
            uint32_t bh[4][2], bl[4][2];
            const uint32_t bOff = (uint32_t)(bRow * SSTRIDE + ks * 16 + bCol) * 2;
#pragma unroll
            for (int nt = 0; nt < 4; nt++) {
                ldsm_x2(bh[nt][0], bh[nt][1], sBh + bOff + nt * 8 * SSTRIDE * 2);
                ldsm_x2(bl[nt][0], bl[nt][1], sBl + bOff + nt * 8 * SSTRIDE * 2);
            }
            const uint32_t aOff = (uint32_t)(aRow * SSTRIDE + ks * 16 + aCol) * 2;
#pragma unroll
            for (int mt = 0; mt < 4; mt++) {
                uint32_t ah[4], al[4];
                ldsm_x4(ah[0], ah[1], ah[2], ah[3], sAh + aOff + mt * 16 * SSTRIDE * 2);
                ldsm_x4(al[0], al[1], al[2], al[3], sAl + aOff + mt * 16 * SSTRIDE * 2);
#pragma unroll
                for (int nt = 0; nt < 4; nt++) {
                    mma_bf16(acc[mt][nt], ah, bh[nt]);
                    mma_bf16(acc[mt][nt], ah, bl[nt]);
                    mma_bf16(acc[mt][nt], al, bh[nt]);
                }
            }
        }
    }

    // ---- epilogue ----
    const int qrow = lid >> 2;
    const int qcol = (lid & 3) * 2;
#pragma unroll
    for (int mt = 0; mt < 4; mt++) {
        const int r0g = row0 + warpM + mt * 16 + qrow;
#pragma unroll
        for (int nt = 0; nt < 4; nt++) {
            const int cg = col0 + warpN + nt * 8 + qcol;
            float v0 = alpha * acc[mt][nt][0];
            float v1 = alpha * acc[mt][nt][1];
            float v2 = alpha * acc[mt][nt][2];
            float v3 = alpha * acc[mt][nt][3];
            if (split_out) {
                __nv_bfloat16 h0 = __float2bfloat16(v0), h1 = __float2bfloat16(v1);
                __nv_bfloat16 h2 = __float2bfloat16(v2), h3 = __float2bfloat16(v3);
                uint32_t hi0 = pk2(h0, h1), hi1 = pk2(h2, h3);
                uint32_t lo0 = pk2(__float2bfloat16(v0 - __bfloat162float(h0)),
                                   __float2bfloat16(v1 - __bfloat162float(h1)));
                uint32_t lo1 = pk2(__float2bfloat16(v2 - __bfloat162float(h2)),
                                   __float2bfloat16(v3 - __bfloat162float(h3)));
                *(uint32_t*)&Ch[(size_t)r0g * N + cg]       = hi0;
                *(uint32_t*)&Cl[(size_t)r0g * N + cg]       = lo0;
                *(uint32_t*)&Ch[(size_t)(r0g + 8) * N + cg] = hi1;
                *(uint32_t*)&Cl[(size_t)(r0g + 8) * N + cg] = lo1;
            } else {
                float2 a0 = {v0, v1}, a1 = {v2, v3};
                *(float2*)&Cf[(size_t)r0g * N + cg]       = a0;
                *(float2*)&Cf[(size_t)(r0g + 8) * N + cg] = a1;
            }
        }
    }
}

// ---------------- mma.sync flash attention, 3-stage cp.async ----------------
// CTA = (q-block of 128, head), 8 warps (256 thr), warp = 16 q-rows.
// K/V hi/lo tiles (64 keys x 128 dims) ride a 3-stage cp.async ring.
#define AS 136                                  // smem row stride (elems)
#define ATILE_B  (64 * AS * 2)                  // 17408 B per array tile
#define ASTAGE_B (4 * ATILE_B)                  // 69632 B per stage
#define ATTN_SMEM (3 * ASTAGE_B)                // 208896 B

__global__ __launch_bounds__(256) void attn_mma(
    const __nv_bfloat16* __restrict__ Qh, const __nv_bfloat16* __restrict__ Ql,
    const __nv_bfloat16* __restrict__ Kh, const __nv_bfloat16* __restrict__ Kl,
    const __nv_bfloat16* __restrict__ Vh, const __nv_bfloat16* __restrict__ Vl,
    __nv_bfloat16* __restrict__ Oh, __nv_bfloat16* __restrict__ Ol)
{
    extern __shared__ char dsm[];
    const uint32_t sb = smem_u32(dsm);

    const int tid = threadIdx.x;
    const int wid = tid >> 5;
    const int lid = tid & 31;
    const int qb = blockIdx.x;
    const int q0 = qb * 128;
    const int h  = blockIdx.y;
    const size_t hoff = (size_t)h * HDIM;

    // ---- stage Q (128 rows hi/lo) into smem, ldmatrix to regs ----
    {
        const int lr = tid >> 1;               // 0..127
        const int lhalf = (tid & 1) * 64;
        const __nv_bfloat16* gqh = Qh + (size_t)(q0 + lr) * HID + hoff + lhalf;
        const __nv_bfloat16* gql = Ql + (size_t)(q0 + lr) * HID + hoff + lhalf;
        __nv_bfloat16* sQh = (__nv_bfloat16*)dsm;
        __nv_bfloat16* sQl = sQh + 128 * AS;
#pragma unroll
        for (int i = 0; i < 8; i++) {
            *(uint4*)&sQh[lr * AS + lhalf + i * 8] = *(const uint4*)(gqh + i * 8);
            *(uint4*)&sQl[lr * AS + lhalf + i * 8] = *(const uint4*)(gql + i * 8);
        }
    }
    __syncthreads();
    uint32_t qfh[8][4], qfl[8][4];
    {
        const uint32_t uQh = sb;
        const uint32_t uQl = sb + 128 * AS * 2;
        const int aRow = wid * 16 + (lid & 15);
        const int aCol = (lid >> 4) * 8;
#pragma unroll
        for (int kt = 0; kt < 8; kt++) {
            uint32_t ao = (uint32_t)(aRow * AS + kt * 16 + aCol) * 2;
            ldsm_x4(qfh[kt][0], qfh[kt][1], qfh[kt][2], qfh[kt][3], uQh + ao);
            ldsm_x4(qfl[kt][0], qfl[kt][1], qfl[kt][2], qfl[kt][3], uQl + ao);
        }
    }
    __syncthreads();   // done with Q staging area before K/V prefetch overwrites it

    // ---- included k-tile list ----
    int tiles[64];
    int ntl = 0;
#pragma unroll 1
    for (int t = 0; t < SEQ / 64; t++) {
        int k0 = t * 64;
        bool inc = (qb == 0) || (t == 0) ||
                   ((k0 + 63 >= q0 - (HALFWIN - 1)) && (k0 <= q0 + 127 + (HALFWIN - 1)));
        if (inc) tiles[ntl++] = t;
    }

    // ---- cp.async prefetch of one K/V hi/lo tile into a stage ----
    const int lr2 = tid >> 2;                  // 0..63 (4 threads per key row)
    const int co  = (tid & 3) * 32;            // elem offset (32 elems = 64B)
    auto prefetch = [&](int t, int st) {
        const size_t gb = (size_t)(t * 64 + lr2) * HID + hoff + co;
        const uint32_t db = sb + st * ASTAGE_B + (uint32_t)(lr2 * AS + co) * 2;
        const __nv_bfloat16* gs[4] = {Kh + gb, Kl + gb, Vh + gb, Vl + gb};
#pragma unroll
        for (int a = 0; a < 4; a++) {
            uint32_t d = db + a * ATILE_B;
#pragma unroll
            for (int i = 0; i < 4; i++)
                cp_async16(d + i * 16, gs[a] + i * 8);
        }
    };

    prefetch(tiles[0], 0); CP_COMMIT();
    if (ntl > 1) { prefetch(tiles[1], 1); CP_COMMIT(); }

    float oAcc[16][4];
#pragma unroll
    for (int i = 0; i < 16; i++)
#pragma unroll
        for (int j = 0; j < 4; j++) oAcc[i][j] = 0.f;
    float mrow[2] = {-1e30f, -1e30f};
    float lsum[2] = {0.f, 0.f};

    const int row0g = q0 + wid * 16 + (lid >> 2);
    const int row1g = row0g + 8;

#pragma unroll 1
    for (int it = 0; it < ntl; it++) {
        const int t  = tiles[it];
        const int k0 = t * 64;

        if (it == ntl - 1) { CP_WAIT0(); } else { CP_WAIT1(); }
        __syncthreads();
        if (it + 2 < ntl) {
            prefetch(tiles[it + 2], (it + 2) % 3);
            CP_COMMIT();
        }

        const uint32_t st  = sb + (it % 3) * ASTAGE_B;
        const uint32_t uKh = st;
        const uint32_t uKl = st + ATILE_B;
        const uint32_t uVh = st + 2 * ATILE_B;
        const uint32_t uVl = st + 3 * ATILE_B;

        // ---- S = Q K^T (hi/lo split, 3 MMAs) ----
        float p[8][4];
#pragma unroll
        for (int i = 0; i < 8; i++)
#pragma unroll
            for (int j = 0; j < 4; j++) p[i][j] = 0.f;

#pragma unroll
        for (int kt = 0; kt < 8; kt++) {
            const uint32_t bOff = (uint32_t)((lid & 7) * AS + kt * 16 + ((lid >> 3) & 1) * 8) * 2;
#pragma unroll
            for (int nt = 0; nt < 8; nt++) {
                uint32_t kbh[2], kbl[2];
                uint32_t o = bOff + nt * 8 * AS * 2;
                ldsm_x2(kbh[0], kbh[1], uKh + o);
                ldsm_x2(kbl[0], kbl[1], uKl + o);
                mma_bf16(p[nt], qfh[kt], kbh);
                mma_bf16(p[nt], qfh[kt], kbl);
                mma_bf16(p[nt], qfl[kt], kbh);
            }
        }

        // ---- mask (edge tiles only). full if every |q-k| < HALFWIN ----
        bool fullTile = (k0 >= q0 - 128) && (k0 <= q0 + 192);
        if (!fullTile) {
            const int cb = k0 + 2 * (lid & 3);
#pragma unroll
            for (int nt = 0; nt < 8; nt++) {
                int kg0 = cb + nt * 8, kg1 = kg0 + 1;
                if (!((row0g < NGLOB) | (kg0 < NGLOB) | (abs(row0g - kg0) < HALFWIN))) p[nt][0] = -1e30f;
                if (!((row0g < NGLOB) | (kg1 < NGLOB) | (abs(row0g - kg1) < HALFWIN))) p[nt][1] = -1e30f;
                if (!((row1g < NGLOB) | (kg0 < NGLOB) | (abs(row1g - kg0) < HALFWIN))) p[nt][2] = -1e30f;
                if (!((row1g < NGLOB) | (kg1 < NGLOB) | (abs(row1g - kg1) < HALFWIN))) p[nt][3] = -1e30f;
            }
        }

        // ---- online softmax ----
        float tm0 = -1e30f, tm1 = -1e30f;
#pragma unroll
        for (int nt = 0; nt < 8; nt++) {
            tm0 = fmaxf(tm0, fmaxf(p[nt][0], p[nt][1]));
            tm1 = fmaxf(tm1, fmaxf(p[nt][2], p[nt][3]));
        }
        tm0 = fmaxf(tm0, __shfl_xor_sync(0xffffffffu, tm0, 1));
        tm0 = fmaxf(tm0, __shfl_xor_sync(0xffffffffu, tm0, 2));
        tm1 = fmaxf(tm1, __shfl_xor_sync(0xffffffffu, tm1, 1));
        tm1 = fmaxf(tm1, __shfl_xor_sync(0xffffffffu, tm1, 2));

        float m0 = fmaxf(mrow[0], tm0);
        float m1 = fmaxf(mrow[1], tm1);
        float f0 = __expf(mrow[0] - m0);
        float f1 = __expf(mrow[1] - m1);
        float rs0 = 0.f, rs1 = 0.f;
#pragma unroll
        for (int nt = 0; nt < 8; nt++) {
            p[nt][0] = __expf(p[nt][0] - m0);
            p[nt][1] = __expf(p[nt][1] - m0);
            p[nt][2] = __expf(p[nt][2] - m1);
            p[nt][3] = __expf(p[nt][3] - m1);
            rs0 += p[nt][0] + p[nt][1];
            rs1 += p[nt][2] + p[nt][3];
        }
        rs0 += __shfl_xor_sync(0xffffffffu, rs0, 1);
        rs0 += __shfl_xor_sync(0xffffffffu, rs0, 2);
        rs1 += __shfl_xor_sync(0xffffffffu, rs1, 1);
        rs1 += __shfl_xor_sync(0xffffffffu, rs1, 2);
        lsum[0] = lsum[0] * f0 + rs0;
        lsum[1] = lsum[1] * f1 + rs1;
        mrow[0] = m0;
        mrow[1] = m1;
#pragma unroll
        for (int nt = 0; nt < 16; nt++) {
            oAcc[nt][0] *= f0;
            oAcc[nt][1] *= f0;
            oAcc[nt][2] *= f1;
            oAcc[nt][3] *= f1;
        }

        // ---- O += P V (P hi/lo split from regs, V via ldmatrix.trans) ----
#pragma unroll
        for (int pk = 0; pk < 4; pk++) {
            uint32_t ah[4], al[4];
            {
                const float* pa = p[2 * pk];
                const float* pb = p[2 * pk + 1];
                __nv_bfloat16 ha0 = __float2bfloat16(pa[0]), ha1 = __float2bfloat16(pa[1]);
                __nv_bfloat16 ha2 = __float2bfloat16(pa[2]), ha3 = __float2bfloat16(pa[3]);
                __nv_bfloat16 hb0 = __float2bfloat16(pb[0]), hb1 = __float2bfloat16(pb[1]);
                __nv_bfloat16 hb2 = __float2bfloat16(pb[2]), hb3 = __float2bfloat16(pb[3]);
                ah[0] = pk2(ha0, ha1);
                ah[1] = pk2(ha2, ha3);
                ah[2] = pk2(hb0, hb1);
                ah[3] = pk2(hb2, hb3);
                al[0] = pk2(__float2bfloat16(pa[0] - __bfloat162float(ha0)),
                            __float2bfloat16(pa[1] - __bfloat162float(ha1)));
                al[1] = pk2(__float2bfloat16(pa[2] - __bfloat162float(ha2)),
                            __float2bfloat16(pa[3] - __bfloat162float(ha3)));
                al[2] = pk2(__float2bfloat16(pb[0] - __bfloat162float(hb0)),
                            __float2bfloat16(pb[1] - __bfloat162float(hb1)));
                al[3] = pk2(__float2bfloat16(pb[2] - __bfloat162float(hb2)),
                            __float2bfloat16(pb[3] - __bfloat162float(hb3)));
            }
            const uint32_t vRow = (uint32_t)((pk * 16 + (lid & 15)) * AS) * 2;
#pragma unroll
            for (int nt = 0; nt < 16; nt++) {
                uint32_t bh[2], bl[2];
                ldsm_x2t(bh[0], bh[1], uVh + vRow + nt * 16);
                ldsm_x2t(bl[0], bl[1], uVl + vRow + nt * 16);
                mma_bf16(oAcc[nt], ah, bh);
                mma_bf16(oAcc[nt], ah, bl);
                mma_bf16(oAcc[nt], al, bh);
            }
        }
    }

    // ---- epilogue: normalize, split to bf16 hi/lo, store ----
    const float inv0 = 1.f / lsum[0];
    const float inv1 = 1.f / lsum[1];
    const int col = (lid & 3) * 2;
#pragma unroll
    for (int nt = 0; nt < 16; nt++) {
        float v0 = oAcc[nt][0] * inv0;
        float v1 = oAcc[nt][1] * inv0;
        float v2 = oAcc[nt][2] * inv1;
        float v3 = oAcc[nt][3] * inv1;
        __nv_bfloat16 h0 = __float2bfloat16(v0), h1 = __float2bfloat16(v1);
        __nv_bfloat16 h2 = __float2bfloat16(v2), h3 = __float2bfloat16(v3);
        size_t o0 = (size_t)row0g * HID + hoff + nt * 8 + col;
        size_t o1 = (size_t)row1g * HID + hoff + nt * 8 + col;
        *(uint32_t*)&Oh[o0] = pk2(h0, h1);
        *(uint32_t*)&Ol[o0] = pk2(__float2bfloat16(v0 - __bfloat162float(h0)),
                                  __float2bfloat16(v1 - __bfloat162float(h1)));
        *(uint32_t*)&Oh[o1] = pk2(h2, h3);
        *(uint32_t*)&Ol[o1] = pk2(__float2bfloat16(v2 - __bfloat162float(h2)),
                                  __float2bfloat16(v3 - __bfloat162float(h3)));
    }
}

// ======================= launch =======================
extern "C" void kernel_launch(void* const* d_in, const int* in_sizes, int n_in,
                              void* d_out, int out_size)
{
    const float* X  = (const float*)d_in[0];
    const float* Wq = (const float*)d_in[1];
    const float* Wk = (const float*)d_in[2];
    const float* Wv = (const float*)d_in[3];
    const float* Wo = (const float*)d_in[4];
    float* out = (float*)d_out;

    __nv_bfloat16 *xh, *xl, *qh, *ql, *kh, *kl, *vh, *vl, *oh, *ol;
    cudaGetSymbolAddress((void**)&xh, g_Xh);
    cudaGetSymbolAddress((void**)&xl, g_Xl);
    cudaGetSymbolAddress((void**)&qh, g_Qh);
    cudaGetSymbolAddress((void**)&ql, g_Ql);
    cudaGetSymbolAddress((void**)&kh, g_Kh);
    cudaGetSymbolAddress((void**)&kl, g_Kl);
    cudaGetSymbolAddress((void**)&vh, g_Vh);
    cudaGetSymbolAddress((void**)&vl, g_Vl);
    cudaGetSymbolAddress((void**)&oh, g_Oh);
    cudaGetSymbolAddress((void**)&ol, g_Ol);
    __nv_bfloat16 *wqh, *wql, *wkh, *wkl, *wvh, *wvl, *woh, *wol;
    cudaGetSymbolAddress((void**)&wqh, g_Wqh);
    cudaGetSymbolAddress((void**)&wql, g_Wql);
    cudaGetSymbolAddress((void**)&wkh, g_Wkh);
    cudaGetSymbolAddress((void**)&wkl, g_Wkl);
    cudaGetSymbolAddress((void**)&wvh, g_Wvh);
    cudaGetSymbolAddress((void**)&wvl, g_Wvl);
    cudaGetSymbolAddress((void**)&woh, g_Woh);
    cudaGetSymbolAddress((void**)&wol, g_Wol);

    cudaFuncSetAttribute(gemm_mma,
                         cudaFuncAttributeMaxDynamicSharedMemorySize, GEMM_SMEM);
    cudaFuncSetAttribute(attn_mma,
                         cudaFuncAttributeMaxDynamicSharedMemorySize, ATTN_SMEM);

    const int n4 = SEQ * HID / 4;
    split_kernel<<<(n4 + 255) / 256, 256>>>(X, xh, xl, n4);
    dim3 tG(HID / 32, HID / 32, 4);
    dim3 tB(32, 8);
    tsplit4_kernel<<<tG, tB>>>(Wq, Wk, Wv, Wo,
                               wqh, wql, wkh, wkl, wvh, wvl, woh, wol);

    dim3 gG(HID / 128, SEQ / 128);   // (16, 32)
    gemm_mma<<<gG, 256, GEMM_SMEM>>>(xh, xl, wqh, wql, nullptr, qh, ql,
                                     SEQ, HID, HID, SCALE, 1);
    gemm_mma<<<gG, 256, GEMM_SMEM>>>(xh, xl, wkh, wkl, nullptr, kh, kl,
                                     SEQ, HID, HID, 1.0f, 1);
    gemm_mma<<<gG, 256, GEMM_SMEM>>>(xh, xl, wvh, wvl, nullptr, vh, vl,
                                     SEQ, HID, HID, 1.0f, 1);

    attn_mma<<<dim3(SEQ / 128, NHEADS), 256, ATTN_SMEM>>>(qh, ql, kh, kl, vh, vl, oh, ol);

    gemm_mma<<<gG, 256, GEMM_SMEM>>>(oh, ol, woh, wol, out, nullptr, nullptr,
                                     SEQ, HID, HID, 1.0f, 0);
}

// round 12
// speedup vs baseline: 1.0226x; 1.0226x over previous
#include <cuda_runtime.h>
#include <cuda_bf16.h>
#include <cstdint>
#include <math.h>

#define SEQ     4096
#define HID     2048
#define NHEADS  16
#define HDIM    128
#define NGLOB   16
#define HALFWIN 256
#define SCALE   0.08838834764831845f   // 128^-0.5

// ---------------- scratch (static device arrays) ----------------
__device__ __nv_bfloat16 g_Xh[SEQ * HID], g_Xl[SEQ * HID];
__device__ __nv_bfloat16 g_Qh[SEQ * HID], g_Ql[SEQ * HID];
__device__ __nv_bfloat16 g_Kh[SEQ * HID], g_Kl[SEQ * HID];
__device__ __nv_bfloat16 g_Vh[SEQ * HID], g_Vl[SEQ * HID];
__device__ __nv_bfloat16 g_Oh[SEQ * HID], g_Ol[SEQ * HID];
__device__ __nv_bfloat16 g_Wqh[HID * HID], g_Wql[HID * HID];
__device__ __nv_bfloat16 g_Wkh[HID * HID], g_Wkl[HID * HID];
__device__ __nv_bfloat16 g_Wvh[HID * HID], g_Wvl[HID * HID];
__device__ __nv_bfloat16 g_Woh[HID * HID], g_Wol[HID * HID];

// ---------------- asm helpers (compute_103-legal) ----------------
__device__ __forceinline__ uint32_t smem_u32(const void* p) {
    uint32_t a;
    asm("{ .reg .u64 t; cvta.to.shared.u64 t, %1; cvt.u32.u64 %0, t; }" : "=r"(a) : "l"(p));
    return a;
}
__device__ __forceinline__ void ldsm_x4(uint32_t& r0, uint32_t& r1, uint32_t& r2,
                                        uint32_t& r3, uint32_t addr) {
    asm volatile("ldmatrix.sync.aligned.m8n8.x4.shared.b16 {%0,%1,%2,%3}, [%4];"
                 : "=r"(r0), "=r"(r1), "=r"(r2), "=r"(r3) : "r"(addr));
}
__device__ __forceinline__ void ldsm_x2(uint32_t& r0, uint32_t& r1, uint32_t addr) {
    asm volatile("ldmatrix.sync.aligned.m8n8.x2.shared.b16 {%0,%1}, [%2];"
                 : "=r"(r0), "=r"(r1) : "r"(addr));
}
__device__ __forceinline__ void ldsm_x2t(uint32_t& r0, uint32_t& r1, uint32_t addr) {
    asm volatile("ldmatrix.sync.aligned.m8n8.x2.trans.shared.b16 {%0,%1}, [%2];"
                 : "=r"(r0), "=r"(r1) : "r"(addr));
}
__device__ __forceinline__ void mma_bf16(float* c, const uint32_t* a, const uint32_t* b) {
    asm volatile(
        "mma.sync.aligned.m16n8k16.row.col.f32.bf16.bf16.f32 "
        "{%0,%1,%2,%3}, {%4,%5,%6,%7}, {%8,%9}, {%0,%1,%2,%3};"
        : "+f"(c[0]), "+f"(c[1]), "+f"(c[2]), "+f"(c[3])
        : "r"(a[0]), "r"(a[1]), "r"(a[2]), "r"(a[3]), "r"(b[0]), "r"(b[1]));
}
__device__ __forceinline__ void cp_async16(uint32_t saddr, const void* g) {
    asm volatile("cp.async.cg.shared.global [%0], [%1], 16;" :: "r"(saddr), "l"(g));
}
#define CP_COMMIT() asm volatile("cp.async.commit_group;" ::: "memory")
#define CP_WAIT0()  asm volatile("cp.async.wait_group 0;" ::: "memory")
#define CP_WAIT1()  asm volatile("cp.async.wait_group 1;" ::: "memory")

__device__ __forceinline__ uint32_t pk2(__nv_bfloat16 a, __nv_bfloat16 b) {
    __nv_bfloat162 t = __halves2bfloat162(a, b);   // a -> low half
    return *(uint32_t*)&t;
}

// ---------------- conversion kernels ----------------
__global__ __launch_bounds__(256) void split_kernel(
    const float* __restrict__ x, __nv_bfloat16* __restrict__ h,
    __nv_bfloat16* __restrict__ l, int n4)
{
    int i = blockIdx.x * blockDim.x + threadIdx.x;
    if (i >= n4) return;
    float4 v = ((const float4*)x)[i];
    __nv_bfloat16 h0 = __float2bfloat16(v.x);
    __nv_bfloat16 h1 = __float2bfloat16(v.y);
    __nv_bfloat16 h2 = __float2bfloat16(v.z);
    __nv_bfloat16 h3 = __float2bfloat16(v.w);
    __nv_bfloat16 l0 = __float2bfloat16(v.x - __bfloat162float(h0));
    __nv_bfloat16 l1 = __float2bfloat16(v.y - __bfloat162float(h1));
    __nv_bfloat16 l2 = __float2bfloat16(v.z - __bfloat162float(h2));
    __nv_bfloat16 l3 = __float2bfloat16(v.w - __bfloat162float(h3));
    ((__nv_bfloat162*)h)[2 * i]     = __halves2bfloat162(h0, h1);
    ((__nv_bfloat162*)h)[2 * i + 1] = __halves2bfloat162(h2, h3);
    ((__nv_bfloat162*)l)[2 * i]     = __halves2bfloat162(l0, l1);
    ((__nv_bfloat162*)l)[2 * i + 1] = __halves2bfloat162(l2, l3);
}

// 4 weight transposes in one launch: blockIdx.z selects the matrix.
__global__ __launch_bounds__(256) void tsplit4_kernel(
    const float* __restrict__ W0, const float* __restrict__ W1,
    const float* __restrict__ W2, const float* __restrict__ W3,
    __nv_bfloat16* __restrict__ T0h, __nv_bfloat16* __restrict__ T0l,
    __nv_bfloat16* __restrict__ T1h, __nv_bfloat16* __restrict__ T1l,
    __nv_bfloat16* __restrict__ T2h, __nv_bfloat16* __restrict__ T2l,
    __nv_bfloat16* __restrict__ T3h, __nv_bfloat16* __restrict__ T3l)
{
    const float* W;
    __nv_bfloat16 *Th, *Tl;
    switch (blockIdx.z) {
        case 0: W = W0; Th = T0h; Tl = T0l; break;
        case 1: W = W1; Th = T1h; Tl = T1l; break;
        case 2: W = W2; Th = T2h; Tl = T2l; break;
        default: W = W3; Th = T3h; Tl = T3l; break;
    }
    __shared__ float t[32][33];
    int tx = threadIdx.x, ty = threadIdx.y;
    int bx = blockIdx.x * 32;   // N
    int by = blockIdx.y * 32;   // K
#pragma unroll
    for (int j = 0; j < 32; j += 8)
        t[ty + j][tx] = W[(size_t)(by + ty + j) * HID + bx + tx];
    __syncthreads();
#pragma unroll
    for (int j = 0; j < 32; j += 8) {
        float v = t[tx][ty + j];
        __nv_bfloat16 hb = __float2bfloat16(v);
        float lo = v - __bfloat162float(hb);
        size_t o = (size_t)(bx + ty + j) * HID + by + tx;
        Th[o] = hb;
        Tl[o] = __float2bfloat16(lo);
    }
}

// ---------------- HMMA bf16-split GEMM ----------------
// C = alpha * (Ah+Al)[M,K] @ (Bh+Bl)^T  (Bt stored [N][K] K-major)
// CTA 128x256, BK=32, 8 warps 2x4, warp tile 64x64.
// 2-stage cp.async ring, ONE __syncthreads per chunk:
//   wait0 -> sync -> prefetch(c+1) -> compute(c)
// (prefetch at iter c overwrites the stage used by compute(c-1), which the
//  sync just fenced; chunk c's cp group had all of compute(c-1) to land.)
#define BKC 32
#define SSTR 40                             // elems per smem row (80 B)
#define ATILE_BY (128 * SSTR * 2)           // 10240
#define BTILE_BY (256 * SSTR * 2)           // 20480
#define GSTAGE   (2 * ATILE_BY + 2 * BTILE_BY)  // 61440
#define GEMM_SMEM (2 * GSTAGE)              // 122880

__global__ __launch_bounds__(256) void gemm_mma(
    const __nv_bfloat16* __restrict__ Ah, const __nv_bfloat16* __restrict__ Al,
    const __nv_bfloat16* __restrict__ Bth, const __nv_bfloat16* __restrict__ Btl,
    float* __restrict__ Cf, __nv_bfloat16* __restrict__ Ch, __nv_bfloat16* __restrict__ Cl,
    int M, int N, int K, float alpha, int split_out)
{
    extern __shared__ char dsm[];
    const uint32_t sb = smem_u32(dsm);
    const int tid = threadIdx.x;
    const int wid = tid >> 5;
    const int lid = tid & 31;
    const int row0 = blockIdx.y * 128;
    const int col0 = blockIdx.x * 256;

    // A load mapping: 2 threads per row, 16 elems (32B) each
    const int lrA = tid >> 1;
    const int haA = (tid & 1) * 16;
    const __nv_bfloat16* gAh = Ah + (size_t)(row0 + lrA) * K + haA;
    const __nv_bfloat16* gAl = Al + (size_t)(row0 + lrA) * K + haA;
    const uint32_t soA = (uint32_t)(lrA * SSTR + haA) * 2;
    // B load mapping: 1 thread per row, 32 elems (64B)
    const __nv_bfloat16* gBh = Bth + (size_t)(col0 + tid) * K;
    const __nv_bfloat16* gBl = Btl + (size_t)(col0 + tid) * K;
    const uint32_t soB = (uint32_t)(tid * SSTR) * 2;

    const int warpM = (wid >> 2) * 64;
    const int warpN = (wid & 3) * 64;
    const int aRow = warpM + (lid & 15);
    const int aCol = (lid >> 4) * 8;
    const int bRow = warpN + (lid & 7);
    const int bCol = ((lid >> 3) & 1) * 8;

    float acc[4][8][4];
#pragma unroll
    for (int i = 0; i < 4; i++)
#pragma unroll
        for (int j = 0; j < 8; j++)
#pragma unroll
            for (int k = 0; k < 4; k++) acc[i][j][k] = 0.f;

    auto prefetch = [&](int c, int st) {
        const uint32_t base = sb + st * GSTAGE;
        const __nv_bfloat16* a0 = gAh + c * BKC;
        const __nv_bfloat16* a1 = gAl + c * BKC;
        const __nv_bfloat16* b0 = gBh + c * BKC;
        const __nv_bfloat16* b1 = gBl + c * BKC;
        cp_async16(base + soA,            a0); cp_async16(base + soA + 16,            a0 + 8);
        cp_async16(base + ATILE_BY + soA, a1); cp_async16(base + ATILE_BY + soA + 16, a1 + 8);
        const uint32_t bb = base + 2 * ATILE_BY + soB;
#pragma unroll
        for (int i = 0; i < 4; i++) cp_async16(bb + i * 16, b0 + i * 8);
        const uint32_t bc = bb + BTILE_BY;
#pragma unroll
        for (int i = 0; i < 4; i++) cp_async16(bc + i * 16, b1 + i * 8);
    };

    prefetch(0, 0);
    CP_COMMIT();

    const int nch = K / BKC;
    for (int c = 0; c < nch; c++) {
        CP_WAIT0();
        __syncthreads();
        if (c + 1 < nch) {
            prefetch(c + 1, (c + 1) & 1);
            CP_COMMIT();
        }

        const uint32_t st  = sb + (c & 1) * GSTAGE;
        const uint32_t sAhU = st;
        const uint32_t sAlU = st + ATILE_BY;
        const uint32_t sBhU = st + 2 * ATILE_BY;
        const uint32_t sBlU = st + 2 * ATILE_BY + BTILE_BY;

#pragma unroll
        for (int ks = 0; ks < 2; ks++) {
            uint32_t bh[8][2], bl[8][2];
            const uint32_t bOff = (uint32_t)(bRow * SSTR + ks * 16 + bCol) * 2;
#pragma unroll
            for (int nt = 0; nt < 8; nt++) {
                ldsm_x2(bh[nt][0], bh[nt][1], sBhU + bOff + nt * 8 * SSTR * 2);
                ldsm_x2(bl[nt][0], bl[nt][1], sBlU + bOff + nt * 8 * SSTR * 2);
            }
            const uint32_t aOff = (uint32_t)(aRow * SSTR + ks * 16 + aCol) * 2;
#pragma unroll
            for (int mt = 0; mt < 4; mt++) {
                uint32_t ah[4], al[4];
                ldsm_x4(ah[0], ah[1], ah[2], ah[3], sAhU + aOff + mt * 16 * SSTR * 2);
                ldsm_x4(al[0], al[1], al[2], al[3], sAlU + aOff + mt * 16 * SSTR * 2);
#pragma unroll
                for (int nt = 0; nt < 8; nt++) {
                    mma_bf16(acc[mt][nt], ah, bh[nt]);
                    mma_bf16(acc[mt][nt], ah, bl[nt]);
                    mma_bf16(acc[mt][nt], al, bh[nt]);
                }
            }
        }
    }

    // ---- epilogue ----
    const int qrow = lid >> 2;
    const int qcol = (lid & 3) * 2;
#pragma unroll
    for (int mt = 0; mt < 4; mt++) {
        const int r0g = row0 + warpM + mt * 16 + qrow;
#pragma unroll
        for (int nt = 0; nt < 8; nt++) {
            const int cg = col0 + warpN + nt * 8 + qcol;
            float v0 = alpha * acc[mt][nt][0];
            float v1 = alpha * acc[mt][nt][1];
            float v2 = alpha * acc[mt][nt][2];
            float v3 = alpha * acc[mt][nt][3];
            if (split_out) {
                __nv_bfloat16 h0 = __float2bfloat16(v0), h1 = __float2bfloat16(v1);
                __nv_bfloat16 h2 = __float2bfloat16(v2), h3 = __float2bfloat16(v3);
                uint32_t hi0 = pk2(h0, h1), hi1 = pk2(h2, h3);
                uint32_t lo0 = pk2(__float2bfloat16(v0 - __bfloat162float(h0)),
                                   __float2bfloat16(v1 - __bfloat162float(h1)));
                uint32_t lo1 = pk2(__float2bfloat16(v2 - __bfloat162float(h2)),
                                   __float2bfloat16(v3 - __bfloat162float(h3)));
                *(uint32_t*)&Ch[(size_t)r0g * N + cg]       = hi0;
                *(uint32_t*)&Cl[(size_t)r0g * N + cg]       = lo0;
                *(uint32_t*)&Ch[(size_t)(r0g + 8) * N + cg] = hi1;
                *(uint32_t*)&Cl[(size_t)(r0g + 8) * N + cg] = lo1;
            } else {
                float2 a0 = {v0, v1}, a1 = {v2, v3};
                *(float2*)&Cf[(size_t)r0g * N + cg]       = a0;
                *(float2*)&Cf[(size_t)(r0g + 8) * N + cg] = a1;
            }
        }
    }
}

// ---------------- mma.sync flash attention, 3-stage cp.async ----------------
// CTA = (q-block of 128, head), 8 warps (256 thr), warp = 16 q-rows.
// K/V hi/lo tiles (64 keys x 128 dims) ride a 3-stage cp.async ring.
#define AS 136                                  // smem row stride (elems)
#define ATILE_B  (64 * AS * 2)                  // 17408 B per array tile
#define ASTAGE_B (4 * ATILE_B)                  // 69632 B per stage
#define ATTN_SMEM (3 * ASTAGE_B)                // 208896 B

__global__ __launch_bounds__(256) void attn_mma(
    const __nv_bfloat16* __restrict__ Qh, const __nv_bfloat16* __restrict__ Ql,
    const __nv_bfloat16* __restrict__ Kh, const __nv_bfloat16* __restrict__ Kl,
    const __nv_bfloat16* __restrict__ Vh, const __nv_bfloat16* __restrict__ Vl,
    __nv_bfloat16* __restrict__ Oh, __nv_bfloat16* __restrict__ Ol)
{
    extern __shared__ char dsm[];
    const uint32_t sb = smem_u32(dsm);

    const int tid = threadIdx.x;
    const int wid = tid >> 5;
    const int lid = tid & 31;
    const int qb = blockIdx.x;
    const int q0 = qb * 128;
    const int h  = blockIdx.y;
    const size_t hoff = (size_t)h * HDIM;

    // ---- stage Q (128 rows hi/lo) into smem, ldmatrix to regs ----
    {
        const int lr = tid >> 1;               // 0..127
        const int lhalf = (tid & 1) * 64;
        const __nv_bfloat16* gqh = Qh + (size_t)(q0 + lr) * HID + hoff + lhalf;
        const __nv_bfloat16* gql = Ql + (size_t)(q0 + lr) * HID + hoff + lhalf;
        __nv_bfloat16* sQh = (__nv_bfloat16*)dsm;
        __nv_bfloat16* sQl = sQh + 128 * AS;
#pragma unroll
        for (int i = 0; i < 8; i++) {
            *(uint4*)&sQh[lr * AS + lhalf + i * 8] = *(const uint4*)(gqh + i * 8);
            *(uint4*)&sQl[lr * AS + lhalf + i * 8] = *(const uint4*)(gql + i * 8);
        }
    }
    __syncthreads();
    uint32_t qfh[8][4], qfl[8][4];
    {
        const uint32_t uQh = sb;
        const uint32_t uQl = sb + 128 * AS * 2;
        const int aRow = wid * 16 + (lid & 15);
        const int aCol = (lid >> 4) * 8;
#pragma unroll
        for (int kt = 0; kt < 8; kt++) {
            uint32_t ao = (uint32_t)(aRow * AS + kt * 16 + aCol) * 2;
            ldsm_x4(qfh[kt][0], qfh[kt][1], qfh[kt][2], qfh[kt][3], uQh + ao);
            ldsm_x4(qfl[kt][0], qfl[kt][1], qfl[kt][2], qfl[kt][3], uQl + ao);
        }
    }
    __syncthreads();   // done with Q staging area before K/V prefetch overwrites it

    // ---- included k-tile list ----
    int tiles[64];
    int ntl = 0;
#pragma unroll 1
    for (int t = 0; t < SEQ / 64; t++) {
        int k0 = t * 64;
        bool inc = (qb == 0) || (t == 0) ||
                   ((k0 + 63 >= q0 - (HALFWIN - 1)) && (k0 <= q0 + 127 + (HALFWIN - 1)));
        if (inc) tiles[ntl++] = t;
    }

    // ---- cp.async prefetch of one K/V hi/lo tile into a stage ----
    const int lr2 = tid >> 2;                  // 0..63 (4 threads per key row)
    const int co  = (tid & 3) * 32;            // elem offset (32 elems = 64B)
    auto prefetch = [&](int t, int st) {
        const size_t gb = (size_t)(t * 64 + lr2) * HID + hoff + co;
        const uint32_t db = sb + st * ASTAGE_B + (uint32_t)(lr2 * AS + co) * 2;
        const __nv_bfloat16* gs[4] = {Kh + gb, Kl + gb, Vh + gb, Vl + gb};
#pragma unroll
        for (int a = 0; a < 4; a++) {
            uint32_t d = db + a * ATILE_B;
#pragma unroll
            for (int i = 0; i < 4; i++)
                cp_async16(d + i * 16, gs[a] + i * 8);
        }
    };

    prefetch(tiles[0], 0); CP_COMMIT();
    if (ntl > 1) { prefetch(tiles[1], 1); CP_COMMIT(); }

    float oAcc[16][4];
#pragma unroll
    for (int i = 0; i < 16; i++)
#pragma unroll
        for (int j = 0; j < 4; j++) oAcc[i][j] = 0.f;
    float mrow[2] = {-1e30f, -1e30f};
    float lsum[2] = {0.f, 0.f};

    const int row0g = q0 + wid * 16 + (lid >> 2);
    const int row1g = row0g + 8;

#pragma unroll 1
    for (int it = 0; it < ntl; it++) {
        const int t  = tiles[it];
        const int k0 = t * 64;

        if (it == ntl - 1) { CP_WAIT0(); } else { CP_WAIT1(); }
        __syncthreads();
        if (it + 2 < ntl) {
            prefetch(tiles[it + 2], (it + 2) % 3);
            CP_COMMIT();
        }

        const uint32_t st  = sb + (it % 3) * ASTAGE_B;
        const uint32_t uKh = st;
        const uint32_t uKl = st + ATILE_B;
        const uint32_t uVh = st + 2 * ATILE_B;
        const uint32_t uVl = st + 3 * ATILE_B;

        // ---- S = Q K^T (hi/lo split, 3 MMAs) ----
        float p[8][4];
#pragma unroll
        for (int i = 0; i < 8; i++)
#pragma unroll
            for (int j = 0; j < 4; j++) p[i][j] = 0.f;

#pragma unroll
        for (int kt = 0; kt < 8; kt++) {
            const uint32_t bOff = (uint32_t)((lid & 7) * AS + kt * 16 + ((lid >> 3) & 1) * 8) * 2;
#pragma unroll
            for (int nt = 0; nt < 8; nt++) {
                uint32_t kbh[2], kbl[2];
                uint32_t o = bOff + nt * 8 * AS * 2;
                ldsm_x2(kbh[0], kbh[1], uKh + o);
                ldsm_x2(kbl[0], kbl[1], uKl + o);
                mma_bf16(p[nt], qfh[kt], kbh);
                mma_bf16(p[nt], qfh[kt], kbl);
                mma_bf16(p[nt], qfl[kt], kbh);
            }
        }

        // ---- mask (edge tiles only). full if every |q-k| < HALFWIN ----
        bool fullTile = (k0 >= q0 - 128) && (k0 <= q0 + 192);
        if (!fullTile) {
            const int cb = k0 + 2 * (lid & 3);
#pragma unroll
            for (int nt = 0; nt < 8; nt++) {
                int kg0 = cb + nt * 8, kg1 = kg0 + 1;
                if (!((row0g < NGLOB) | (kg0 < NGLOB) | (abs(row0g - kg0) < HALFWIN))) p[nt][0] = -1e30f;
                if (!((row0g < NGLOB) | (kg1 < NGLOB) | (abs(row0g - kg1) < HALFWIN))) p[nt][1] = -1e30f;
                if (!((row1g < NGLOB) | (kg0 < NGLOB) | (abs(row1g - kg0) < HALFWIN))) p[nt][2] = -1e30f;
                if (!((row1g < NGLOB) | (kg1 < NGLOB) | (abs(row1g - kg1) < HALFWIN))) p[nt][3] = -1e30f;
            }
        }

        // ---- online softmax ----
        float tm0 = -1e30f, tm1 = -1e30f;
#pragma unroll
        for (int nt = 0; nt < 8; nt++) {
            tm0 = fmaxf(tm0, fmaxf(p[nt][0], p[nt][1]));
            tm1 = fmaxf(tm1, fmaxf(p[nt][2], p[nt][3]));
        }
        tm0 = fmaxf(tm0, __shfl_xor_sync(0xffffffffu, tm0, 1));
        tm0 = fmaxf(tm0, __shfl_xor_sync(0xffffffffu, tm0, 2));
        tm1 = fmaxf(tm1, __shfl_xor_sync(0xffffffffu, tm1, 1));
        tm1 = fmaxf(tm1, __shfl_xor_sync(0xffffffffu, tm1, 2));

        float m0 = fmaxf(mrow[0], tm0);
        float m1 = fmaxf(mrow[1], tm1);
        float f0 = __expf(mrow[0] - m0);
        float f1 = __expf(mrow[1] - m1);
        float rs0 = 0.f, rs1 = 0.f;
#pragma unroll
        for (int nt = 0; nt < 8; nt++) {
            p[nt][0] = __expf(p[nt][0] - m0);
            p[nt][1] = __expf(p[nt][1] - m0);
            p[nt][2] = __expf(p[nt][2] - m1);
            p[nt][3] = __expf(p[nt][3] - m1);
            rs0 += p[nt][0] + p[nt][1];
            rs1 += p[nt][2] + p[nt][3];
        }
        rs0 += __shfl_xor_sync(0xffffffffu, rs0, 1);
        rs0 += __shfl_xor_sync(0xffffffffu, rs0, 2);
        rs1 += __shfl_xor_sync(0xffffffffu, rs1, 1);
        rs1 += __shfl_xor_sync(0xffffffffu, rs1, 2);
        lsum[0] = lsum[0] * f0 + rs0;
        lsum[1] = lsum[1] * f1 + rs1;
        mrow[0] = m0;
        mrow[1] = m1;
#pragma unroll
        for (int nt = 0; nt < 16; nt++) {
            oAcc[nt][0] *= f0;
            oAcc[nt][1] *= f0;
            oAcc[nt][2] *= f1;
            oAcc[nt][3] *= f1;
        }

        // ---- O += P V (P hi/lo split from regs, V via ldmatrix.trans) ----
#pragma unroll
        for (int pk = 0; pk < 4; pk++) {
            uint32_t ah[4], al[4];
            {
                const float* pa = p[2 * pk];
                const float* pb = p[2 * pk + 1];
                __nv_bfloat16 ha0 = __float2bfloat16(pa[0]), ha1 = __float2bfloat16(pa[1]);
                __nv_bfloat16 ha2 = __float2bfloat16(pa[2]), ha3 = __float2bfloat16(pa[3]);
                __nv_bfloat16 hb0 = __float2bfloat16(pb[0]), hb1 = __float2bfloat16(pb[1]);
                __nv_bfloat16 hb2 = __float2bfloat16(pb[2]), hb3 = __float2bfloat16(pb[3]);
                ah[0] = pk2(ha0, ha1);
                ah[1] = pk2(ha2, ha3);
                ah[2] = pk2(hb0, hb1);
                ah[3] = pk2(hb2, hb3);
                al[0] = pk2(__float2bfloat16(pa[0] - __bfloat162float(ha0)),
                            __float2bfloat16(pa[1] - __bfloat162float(ha1)));
                al[1] = pk2(__float2bfloat16(pa[2] - __bfloat162float(ha2)),
                            __float2bfloat16(pa[3] - __bfloat162float(ha3)));
                al[2] = pk2(__float2bfloat16(pb[0] - __bfloat162float(hb0)),
                            __float2bfloat16(pb[1] - __bfloat162float(hb1)));
                al[3] = pk2(__float2bfloat16(pb[2] - __bfloat162float(hb2)),
                            __float2bfloat16(pb[3] - __bfloat162float(hb3)));
            }
            const uint32_t vRow = (uint32_t)((pk * 16 + (lid & 15)) * AS) * 2;
#pragma unroll
            for (int nt = 0; nt < 16; nt++) {
                uint32_t bh[2], bl[2];
                ldsm_x2t(bh[0], bh[1], uVh + vRow + nt * 16);
                ldsm_x2t(bl[0], bl[1], uVl + vRow + nt * 16);
                mma_bf16(oAcc[nt], ah, bh);
                mma_bf16(oAcc[nt], ah, bl);
                mma_bf16(oAcc[nt], al, bh);
            }
        }
    }

    // ---- epilogue: normalize, split to bf16 hi/lo, store ----
    const float inv0 = 1.f / lsum[0];
    const float inv1 = 1.f / lsum[1];
    const int col = (lid & 3) * 2;
#pragma unroll
    for (int nt = 0; nt < 16; nt++) {
        float v0 = oAcc[nt][0] * inv0;
        float v1 = oAcc[nt][1] * inv0;
        float v2 = oAcc[nt][2] * inv1;
        float v3 = oAcc[nt][3] * inv1;
        __nv_bfloat16 h0 = __float2bfloat16(v0), h1 = __float2bfloat16(v1);
        __nv_bfloat16 h2 = __float2bfloat16(v2), h3 = __float2bfloat16(v3);
        size_t o0 = (size_t)row0g * HID + hoff + nt * 8 + col;
        size_t o1 = (size_t)row1g * HID + hoff + nt * 8 + col;
        *(uint32_t*)&Oh[o0] = pk2(h0, h1);
        *(uint32_t*)&Ol[o0] = pk2(__float2bfloat16(v0 - __bfloat162float(h0)),
                                  __float2bfloat16(v1 - __bfloat162float(h1)));
        *(uint32_t*)&Oh[o1] = pk2(h2, h3);
        *(uint32_t*)&Ol[o1] = pk2(__float2bfloat16(v2 - __bfloat162float(h2)),
                                  __float2bfloat16(v3 - __bfloat162float(h3)));
    }
}

// ======================= launch =======================
extern "C" void kernel_launch(void* const* d_in, const int* in_sizes, int n_in,
                              void* d_out, int out_size)
{
    const float* X  = (const float*)d_in[0];
    const float* Wq = (const float*)d_in[1];
    const float* Wk = (const float*)d_in[2];
    const float* Wv = (const float*)d_in[3];
    const float* Wo = (const float*)d_in[4];
    float* out = (float*)d_out;

    __nv_bfloat16 *xh, *xl, *qh, *ql, *kh, *kl, *vh, *vl, *oh, *ol;
    cudaGetSymbolAddress((void**)&xh, g_Xh);
    cudaGetSymbolAddress((void**)&xl, g_Xl);
    cudaGetSymbolAddress((void**)&qh, g_Qh);
    cudaGetSymbolAddress((void**)&ql, g_Ql);
    cudaGetSymbolAddress((void**)&kh, g_Kh);
    cudaGetSymbolAddress((void**)&kl, g_Kl);
    cudaGetSymbolAddress((void**)&vh, g_Vh);
    cudaGetSymbolAddress((void**)&vl, g_Vl);
    cudaGetSymbolAddress((void**)&oh, g_Oh);
    cudaGetSymbolAddress((void**)&ol, g_Ol);
    __nv_bfloat16 *wqh, *wql, *wkh, *wkl, *wvh, *wvl, *woh, *wol;
    cudaGetSymbolAddress((void**)&wqh, g_Wqh);
    cudaGetSymbolAddress((void**)&wql, g_Wql);
    cudaGetSymbolAddress((void**)&wkh, g_Wkh);
    cudaGetSymbolAddress((void**)&wkl, g_Wkl);
    cudaGetSymbolAddress((void**)&wvh, g_Wvh);
    cudaGetSymbolAddress((void**)&wvl, g_Wvl);
    cudaGetSymbolAddress((void**)&woh, g_Woh);
    cudaGetSymbolAddress((void**)&wol, g_Wol);

    cudaFuncSetAttribute(gemm_mma,
                         cudaFuncAttributeMaxDynamicSharedMemorySize, GEMM_SMEM);
    cudaFuncSetAttribute(attn_mma,
                         cudaFuncAttributeMaxDynamicSharedMemorySize, ATTN_SMEM);

    const int n4 = SEQ * HID / 4;
    split_kernel<<<(n4 + 255) / 256, 256>>>(X, xh, xl, n4);
    dim3 tG(HID / 32, HID / 32, 4);
    dim3 tB(32, 8);
    tsplit4_kernel<<<tG, tB>>>(Wq, Wk, Wv, Wo,
                               wqh, wql, wkh, wkl, wvh, wvl, woh, wol);

    dim3 gG(HID / 256, SEQ / 128);   // (8, 32)
    gemm_mma<<<gG, 256, GEMM_SMEM>>>(xh, xl, wqh, wql, nullptr, qh, ql,
                                     SEQ, HID, HID, SCALE, 1);
    gemm_mma<<<gG, 256, GEMM_SMEM>>>(xh, xl, wkh, wkl, nullptr, kh, kl,
                                     SEQ, HID, HID, 1.0f, 1);
    gemm_mma<<<gG, 256, GEMM_SMEM>>>(xh, xl, wvh, wvl, nullptr, vh, vl,
                                     SEQ, HID, HID, 1.0f, 1);

    attn_mma<<<dim3(SEQ / 128, NHEADS), 256, ATTN_SMEM>>>(qh, ql, kh, kl, vh, vl, oh, ol);

    gemm_mma<<<gG, 256, GEMM_SMEM>>>(oh, ol, woh, wol, out, nullptr, nullptr,
                                     SEQ, HID, HID, 1.0f, 0);
}

// round 13
// speedup vs baseline: 1.1442x; 1.1189x over previous
#include <cuda_runtime.h>
#include <cuda_bf16.h>
#include <cstdint>
#include <math.h>

#define SEQ     4096
#define HID     2048
#define NHEADS  16
#define HDIM    128
#define NGLOB   16
#define HALFWIN 256
#define SCALE   0.08838834764831845f   // 128^-0.5

// ---------------- scratch (static device arrays) ----------------
__device__ __nv_bfloat16 g_Xh[SEQ * HID], g_Xl[SEQ * HID];
__device__ __nv_bfloat16 g_Qh[SEQ * HID], g_Ql[SEQ * HID];
__device__ __nv_bfloat16 g_Kh[SEQ * HID], g_Kl[SEQ * HID];
__device__ __nv_bfloat16 g_Vh[SEQ * HID], g_Vl[SEQ * HID];
__device__ __nv_bfloat16 g_Oh[SEQ * HID], g_Ol[SEQ * HID];
__device__ __nv_bfloat16 g_Wqh[HID * HID], g_Wql[HID * HID];
__device__ __nv_bfloat16 g_Wkh[HID * HID], g_Wkl[HID * HID];
__device__ __nv_bfloat16 g_Wvh[HID * HID], g_Wvl[HID * HID];
__device__ __nv_bfloat16 g_Woh[HID * HID], g_Wol[HID * HID];

// ---------------- asm helpers (compute_103-legal) ----------------
__device__ __forceinline__ uint32_t smem_u32(const void* p) {
    uint32_t a;
    asm("{ .reg .u64 t; cvta.to.shared.u64 t, %1; cvt.u32.u64 %0, t; }" : "=r"(a) : "l"(p));
    return a;
}
__device__ __forceinline__ void ldsm_x4(uint32_t& r0, uint32_t& r1, uint32_t& r2,
                                        uint32_t& r3, uint32_t addr) {
    asm volatile("ldmatrix.sync.aligned.m8n8.x4.shared.b16 {%0,%1,%2,%3}, [%4];"
                 : "=r"(r0), "=r"(r1), "=r"(r2), "=r"(r3) : "r"(addr));
}
__device__ __forceinline__ void ldsm_x2(uint32_t& r0, uint32_t& r1, uint32_t addr) {
    asm volatile("ldmatrix.sync.aligned.m8n8.x2.shared.b16 {%0,%1}, [%2];"
                 : "=r"(r0), "=r"(r1) : "r"(addr));
}
__device__ __forceinline__ void ldsm_x2t(uint32_t& r0, uint32_t& r1, uint32_t addr) {
    asm volatile("ldmatrix.sync.aligned.m8n8.x2.trans.shared.b16 {%0,%1}, [%2];"
                 : "=r"(r0), "=r"(r1) : "r"(addr));
}
__device__ __forceinline__ void mma_bf16(float* c, const uint32_t* a, const uint32_t* b) {
    asm volatile(
        "mma.sync.aligned.m16n8k16.row.col.f32.bf16.bf16.f32 "
        "{%0,%1,%2,%3}, {%4,%5,%6,%7}, {%8,%9}, {%0,%1,%2,%3};"
        : "+f"(c[0]), "+f"(c[1]), "+f"(c[2]), "+f"(c[3])
        : "r"(a[0]), "r"(a[1]), "r"(a[2]), "r"(a[3]), "r"(b[0]), "r"(b[1]));
}
__device__ __forceinline__ void cp_async16(uint32_t saddr, const void* g) {
    asm volatile("cp.async.cg.shared.global [%0], [%1], 16;" :: "r"(saddr), "l"(g));
}
#define CP_COMMIT() asm volatile("cp.async.commit_group;" ::: "memory")
#define CP_WAIT0()  asm volatile("cp.async.wait_group 0;" ::: "memory")
#define CP_WAIT1()  asm volatile("cp.async.wait_group 1;" ::: "memory")

__device__ __forceinline__ uint32_t pk2(__nv_bfloat16 a, __nv_bfloat16 b) {
    __nv_bfloat162 t = __halves2bfloat162(a, b);   // a -> low half
    return *(uint32_t*)&t;
}

// ---------------- conversion kernels ----------------
__global__ __launch_bounds__(256) void split_kernel(
    const float* __restrict__ x, __nv_bfloat16* __restrict__ h,
    __nv_bfloat16* __restrict__ l, int n4)
{
    int i = blockIdx.x * blockDim.x + threadIdx.x;
    if (i >= n4) return;
    float4 v = ((const float4*)x)[i];
    __nv_bfloat16 h0 = __float2bfloat16(v.x);
    __nv_bfloat16 h1 = __float2bfloat16(v.y);
    __nv_bfloat16 h2 = __float2bfloat16(v.z);
    __nv_bfloat16 h3 = __float2bfloat16(v.w);
    __nv_bfloat16 l0 = __float2bfloat16(v.x - __bfloat162float(h0));
    __nv_bfloat16 l1 = __float2bfloat16(v.y - __bfloat162float(h1));
    __nv_bfloat16 l2 = __float2bfloat16(v.z - __bfloat162float(h2));
    __nv_bfloat16 l3 = __float2bfloat16(v.w - __bfloat162float(h3));
    ((__nv_bfloat162*)h)[2 * i]     = __halves2bfloat162(h0, h1);
    ((__nv_bfloat162*)h)[2 * i + 1] = __halves2bfloat162(h2, h3);
    ((__nv_bfloat162*)l)[2 * i]     = __halves2bfloat162(l0, l1);
    ((__nv_bfloat162*)l)[2 * i + 1] = __halves2bfloat162(l2, l3);
}

// 4 weight transposes in one launch: blockIdx.z selects the matrix.
__global__ __launch_bounds__(256) void tsplit4_kernel(
    const float* __restrict__ W0, const float* __restrict__ W1,
    const float* __restrict__ W2, const float* __restrict__ W3,
    __nv_bfloat16* __restrict__ T0h, __nv_bfloat16* __restrict__ T0l,
    __nv_bfloat16* __restrict__ T1h, __nv_bfloat16* __restrict__ T1l,
    __nv_bfloat16* __restrict__ T2h, __nv_bfloat16* __restrict__ T2l,
    __nv_bfloat16* __restrict__ T3h, __nv_bfloat16* __restrict__ T3l)
{
    const float* W;
    __nv_bfloat16 *Th, *Tl;
    switch (blockIdx.z) {
        case 0: W = W0; Th = T0h; Tl = T0l; break;
        case 1: W = W1; Th = T1h; Tl = T1l; break;
        case 2: W = W2; Th = T2h; Tl = T2l; break;
        default: W = W3; Th = T3h; Tl = T3l; break;
    }
    __shared__ float t[32][33];
    int tx = threadIdx.x, ty = threadIdx.y;
    int bx = blockIdx.x * 32;   // N
    int by = blockIdx.y * 32;   // K
#pragma unroll
    for (int j = 0; j < 32; j += 8)
        t[ty + j][tx] = W[(size_t)(by + ty + j) * HID + bx + tx];
    __syncthreads();
#pragma unroll
    for (int j = 0; j < 32; j += 8) {
        float v = t[tx][ty + j];
        __nv_bfloat16 hb = __float2bfloat16(v);
        float lo = v - __bfloat162float(hb);
        size_t o = (size_t)(bx + ty + j) * HID + by + tx;
        Th[o] = hb;
        Tl[o] = __float2bfloat16(lo);
    }
}

// ---------------- HMMA bf16-split GEMM ----------------
// C = alpha * (Ah+Al)[M,K] @ (Bh+Bl)^T  (Bt stored [N][K] K-major)
// CTA 128x128, BK=32, 8 warps 2x4, warp tile 64x32.
// REGISTER-CAPPED (__launch_bounds__(256,2)) so 2 CTAs/SM are resident:
// the R9-R12 kernels were register-limited to 1 CTA/SM (239 regs x 256 thr
// = the whole 64K regfile), which capped tensor-pipe util at ~43%.
// 2-stage cp.async ring, one __syncthreads per chunk:
//   wait -> sync -> prefetch(c+1) -> compute(c)
#define BKC 32
#define SSTR 40                             // elems per smem row (80 B)
#define GTILE_BY (128 * SSTR * 2)           // 10240 per array tile
#define GSTAGE   (4 * GTILE_BY)             // 40960
#define GEMM_SMEM (2 * GSTAGE)              // 81920  -> 2 CTAs/SM

__global__ __launch_bounds__(256, 2) void gemm_mma(
    const __nv_bfloat16* __restrict__ Ah, const __nv_bfloat16* __restrict__ Al,
    const __nv_bfloat16* __restrict__ Bth, const __nv_bfloat16* __restrict__ Btl,
    float* __restrict__ Cf, __nv_bfloat16* __restrict__ Ch, __nv_bfloat16* __restrict__ Cl,
    int M, int N, int K, float alpha, int split_out)
{
    extern __shared__ char dsm[];
    const uint32_t sb = smem_u32(dsm);
    const int tid = threadIdx.x;
    const int wid = tid >> 5;
    const int lid = tid & 31;
    const int row0 = blockIdx.y * 128;
    const int col0 = blockIdx.x * 128;

    // load mapping: 2 threads per 128-row tile row, 16 elems (32B) each
    const int lr = tid >> 1;
    const int ha = (tid & 1) * 16;
    const __nv_bfloat16* gAh = Ah  + (size_t)(row0 + lr) * K + ha;
    const __nv_bfloat16* gAl = Al  + (size_t)(row0 + lr) * K + ha;
    const __nv_bfloat16* gBh = Bth + (size_t)(col0 + lr) * K + ha;
    const __nv_bfloat16* gBl = Btl + (size_t)(col0 + lr) * K + ha;
    const uint32_t so = (uint32_t)(lr * SSTR + ha) * 2;

    const int warpM = (wid >> 2) * 64;
    const int warpN = (wid & 3) * 32;
    const int aRow = warpM + (lid & 15);
    const int aCol = (lid >> 4) * 8;
    const int bRow = warpN + (lid & 7);
    const int bCol = ((lid >> 3) & 1) * 8;

    float acc[4][4][4];
#pragma unroll
    for (int i = 0; i < 4; i++)
#pragma unroll
        for (int j = 0; j < 4; j++)
#pragma unroll
            for (int k = 0; k < 4; k++) acc[i][j][k] = 0.f;

    auto prefetch = [&](int c, int st) {
        const uint32_t base = sb + st * GSTAGE + so;
        const __nv_bfloat16* a0 = gAh + c * BKC;
        const __nv_bfloat16* a1 = gAl + c * BKC;
        const __nv_bfloat16* b0 = gBh + c * BKC;
        const __nv_bfloat16* b1 = gBl + c * BKC;
        cp_async16(base,                 a0); cp_async16(base + 16,                 a0 + 8);
        cp_async16(base + GTILE_BY,      a1); cp_async16(base + GTILE_BY + 16,      a1 + 8);
        cp_async16(base + 2 * GTILE_BY,  b0); cp_async16(base + 2 * GTILE_BY + 16,  b0 + 8);
        cp_async16(base + 3 * GTILE_BY,  b1); cp_async16(base + 3 * GTILE_BY + 16,  b1 + 8);
    };

    prefetch(0, 0);
    CP_COMMIT();

    const int nch = K / BKC;
    for (int c = 0; c < nch; c++) {
        CP_WAIT0();
        __syncthreads();
        if (c + 1 < nch) {
            prefetch(c + 1, (c + 1) & 1);
            CP_COMMIT();
        }

        const uint32_t st   = sb + (c & 1) * GSTAGE;
        const uint32_t sAhU = st;
        const uint32_t sAlU = st + GTILE_BY;
        const uint32_t sBhU = st + 2 * GTILE_BY;
        const uint32_t sBlU = st + 3 * GTILE_BY;

#pragma unroll
        for (int ks = 0; ks < 2; ks++) {
            uint32_t bh[4][2], bl[4][2];
            const uint32_t bOff = (uint32_t)(bRow * SSTR + ks * 16 + bCol) * 2;
#pragma unroll
            for (int nt = 0; nt < 4; nt++) {
                ldsm_x2(bh[nt][0], bh[nt][1], sBhU + bOff + nt * 8 * SSTR * 2);
                ldsm_x2(bl[nt][0], bl[nt][1], sBlU + bOff + nt * 8 * SSTR * 2);
            }
            const uint32_t aOff = (uint32_t)(aRow * SSTR + ks * 16 + aCol) * 2;
#pragma unroll
            for (int mt = 0; mt < 4; mt++) {
                uint32_t ah[4], al[4];
                ldsm_x4(ah[0], ah[1], ah[2], ah[3], sAhU + aOff + mt * 16 * SSTR * 2);
                ldsm_x4(al[0], al[1], al[2], al[3], sAlU + aOff + mt * 16 * SSTR * 2);
#pragma unroll
                for (int nt = 0; nt < 4; nt++) {
                    mma_bf16(acc[mt][nt], ah, bh[nt]);
                    mma_bf16(acc[mt][nt], ah, bl[nt]);
                    mma_bf16(acc[mt][nt], al, bh[nt]);
                }
            }
        }
    }

    // ---- epilogue ----
    const int qrow = lid >> 2;
    const int qcol = (lid & 3) * 2;
#pragma unroll
    for (int mt = 0; mt < 4; mt++) {
        const int r0g = row0 + warpM + mt * 16 + qrow;
#pragma unroll
        for (int nt = 0; nt < 4; nt++) {
            const int cg = col0 + warpN + nt * 8 + qcol;
            float v0 = alpha * acc[mt][nt][0];
            float v1 = alpha * acc[mt][nt][1];
            float v2 = alpha * acc[mt][nt][2];
            float v3 = alpha * acc[mt][nt][3];
            if (split_out) {
                __nv_bfloat16 h0 = __float2bfloat16(v0), h1 = __float2bfloat16(v1);
                __nv_bfloat16 h2 = __float2bfloat16(v2), h3 = __float2bfloat16(v3);
                uint32_t hi0 = pk2(h0, h1), hi1 = pk2(h2, h3);
                uint32_t lo0 = pk2(__float2bfloat16(v0 - __bfloat162float(h0)),
                                   __float2bfloat16(v1 - __bfloat162float(h1)));
                uint32_t lo1 = pk2(__float2bfloat16(v2 - __bfloat162float(h2)),
                                   __float2bfloat16(v3 - __bfloat162float(h3)));
                *(uint32_t*)&Ch[(size_t)r0g * N + cg]       = hi0;
                *(uint32_t*)&Cl[(size_t)r0g * N + cg]       = lo0;
                *(uint32_t*)&Ch[(size_t)(r0g + 8) * N + cg] = hi1;
                *(uint32_t*)&Cl[(size_t)(r0g + 8) * N + cg] = lo1;
            } else {
                float2 a0 = {v0, v1}, a1 = {v2, v3};
                *(float2*)&Cf[(size_t)r0g * N + cg]       = a0;
                *(float2*)&Cf[(size_t)(r0g + 8) * N + cg] = a1;
            }
        }
    }
}

// ---------------- mma.sync flash attention, 3-stage cp.async ----------------
// CTA = (q-block of 128, head), 8 warps (256 thr), warp = 16 q-rows.
// K/V hi/lo tiles (64 keys x 128 dims) ride a 3-stage cp.async ring.
#define AS 136                                  // smem row stride (elems)
#define ATILE_B  (64 * AS * 2)                  // 17408 B per array tile
#define ASTAGE_B (4 * ATILE_B)                  // 69632 B per stage
#define ATTN_SMEM (3 * ASTAGE_B)                // 208896 B

__global__ __launch_bounds__(256) void attn_mma(
    const __nv_bfloat16* __restrict__ Qh, const __nv_bfloat16* __restrict__ Ql,
    const __nv_bfloat16* __restrict__ Kh, const __nv_bfloat16* __restrict__ Kl,
    const __nv_bfloat16* __restrict__ Vh, const __nv_bfloat16* __restrict__ Vl,
    __nv_bfloat16* __restrict__ Oh, __nv_bfloat16* __restrict__ Ol)
{
    extern __shared__ char dsm[];
    const uint32_t sb = smem_u32(dsm);

    const int tid = threadIdx.x;
    const int wid = tid >> 5;
    const int lid = tid & 31;
    const int qb = blockIdx.x;
    const int q0 = qb * 128;
    const int h  = blockIdx.y;
    const size_t hoff = (size_t)h * HDIM;

    // ---- stage Q (128 rows hi/lo) into smem, ldmatrix to regs ----
    {
        const int lr = tid >> 1;               // 0..127
        const int lhalf = (tid & 1) * 64;
        const __nv_bfloat16* gqh = Qh + (size_t)(q0 + lr) * HID + hoff + lhalf;
        const __nv_bfloat16* gql = Ql + (size_t)(q0 + lr) * HID + hoff + lhalf;
        __nv_bfloat16* sQh = (__nv_bfloat16*)dsm;
        __nv_bfloat16* sQl = sQh + 128 * AS;
#pragma unroll
        for (int i = 0; i < 8; i++) {
            *(uint4*)&sQh[lr * AS + lhalf + i * 8] = *(const uint4*)(gqh + i * 8);
            *(uint4*)&sQl[lr * AS + lhalf + i * 8] = *(const uint4*)(gql + i * 8);
        }
    }
    __syncthreads();
    uint32_t qfh[8][4], qfl[8][4];
    {
        const uint32_t uQh = sb;
        const uint32_t uQl = sb + 128 * AS * 2;
        const int aRow = wid * 16 + (lid & 15);
        const int aCol = (lid >> 4) * 8;
#pragma unroll
        for (int kt = 0; kt < 8; kt++) {
            uint32_t ao = (uint32_t)(aRow * AS + kt * 16 + aCol) * 2;
            ldsm_x4(qfh[kt][0], qfh[kt][1], qfh[kt][2], qfh[kt][3], uQh + ao);
            ldsm_x4(qfl[kt][0], qfl[kt][1], qfl[kt][2], qfl[kt][3], uQl + ao);
        }
    }
    __syncthreads();   // done with Q staging area before K/V prefetch overwrites it

    // ---- included k-tile list ----
    int tiles[64];
    int ntl = 0;
#pragma unroll 1
    for (int t = 0; t < SEQ / 64; t++) {
        int k0 = t * 64;
        bool inc = (qb == 0) || (t == 0) ||
                   ((k0 + 63 >= q0 - (HALFWIN - 1)) && (k0 <= q0 + 127 + (HALFWIN - 1)));
        if (inc) tiles[ntl++] = t;
    }

    // ---- cp.async prefetch of one K/V hi/lo tile into a stage ----
    const int lr2 = tid >> 2;                  // 0..63 (4 threads per key row)
    const int co  = (tid & 3) * 32;            // elem offset (32 elems = 64B)
    auto prefetch = [&](int t, int st) {
        const size_t gb = (size_t)(t * 64 + lr2) * HID + hoff + co;
        const uint32_t db = sb + st * ASTAGE_B + (uint32_t)(lr2 * AS + co) * 2;
        const __nv_bfloat16* gs[4] = {Kh + gb, Kl + gb, Vh + gb, Vl + gb};
#pragma unroll
        for (int a = 0; a < 4; a++) {
            uint32_t d = db + a * ATILE_B;
#pragma unroll
            for (int i = 0; i < 4; i++)
                cp_async16(d + i * 16, gs[a] + i * 8);
        }
    };

    prefetch(tiles[0], 0); CP_COMMIT();
    if (ntl > 1) { prefetch(tiles[1], 1); CP_COMMIT(); }

    float oAcc[16][4];
#pragma unroll
    for (int i = 0; i < 16; i++)
#pragma unroll
        for (int j = 0; j < 4; j++) oAcc[i][j] = 0.f;
    float mrow[2] = {-1e30f, -1e30f};
    float lsum[2] = {0.f, 0.f};

    const int row0g = q0 + wid * 16 + (lid >> 2);
    const int row1g = row0g + 8;

#pragma unroll 1
    for (int it = 0; it < ntl; it++) {
        const int t  = tiles[it];
        const int k0 = t * 64;

        if (it == ntl - 1) { CP_WAIT0(); } else { CP_WAIT1(); }
        __syncthreads();
        if (it + 2 < ntl) {
            prefetch(tiles[it + 2], (it + 2) % 3);
            CP_COMMIT();
        }

        const uint32_t st  = sb + (it % 3) * ASTAGE_B;
        const uint32_t uKh = st;
        const uint32_t uKl = st + ATILE_B;
        const uint32_t uVh = st + 2 * ATILE_B;
        const uint32_t uVl = st + 3 * ATILE_B;

        // ---- S = Q K^T (hi/lo split, 3 MMAs) ----
        float p[8][4];
#pragma unroll
        for (int i = 0; i < 8; i++)
#pragma unroll
            for (int j = 0; j < 4; j++) p[i][j] = 0.f;

#pragma unroll
        for (int kt = 0; kt < 8; kt++) {
            const uint32_t bOff = (uint32_t)((lid & 7) * AS + kt * 16 + ((lid >> 3) & 1) * 8) * 2;
#pragma unroll
            for (int nt = 0; nt < 8; nt++) {
                uint32_t kbh[2], kbl[2];
                uint32_t o = bOff + nt * 8 * AS * 2;
                ldsm_x2(kbh[0], kbh[1], uKh + o);
                ldsm_x2(kbl[0], kbl[1], uKl + o);
                mma_bf16(p[nt], qfh[kt], kbh);
                mma_bf16(p[nt], qfh[kt], kbl);
                mma_bf16(p[nt], qfl[kt], kbh);
            }
        }

        // ---- mask (edge tiles only). full if every |q-k| < HALFWIN ----
        bool fullTile = (k0 >= q0 - 128) && (k0 <= q0 + 192);
        if (!fullTile) {
            const int cb = k0 + 2 * (lid & 3);
#pragma unroll
            for (int nt = 0; nt < 8; nt++) {
                int kg0 = cb + nt * 8, kg1 = kg0 + 1;
                if (!((row0g < NGLOB) | (kg0 < NGLOB) | (abs(row0g - kg0) < HALFWIN))) p[nt][0] = -1e30f;
                if (!((row0g < NGLOB) | (kg1 < NGLOB) | (abs(row0g - kg1) < HALFWIN))) p[nt][1] = -1e30f;
                if (!((row1g < NGLOB) | (kg0 < NGLOB) | (abs(row1g - kg0) < HALFWIN))) p[nt][2] = -1e30f;
                if (!((row1g < NGLOB) | (kg1 < NGLOB) | (abs(row1g - kg1) < HALFWIN))) p[nt][3] = -1e30f;
            }
        }

        // ---- online softmax ----
        float tm0 = -1e30f, tm1 = -1e30f;
#pragma unroll
        for (int nt = 0; nt < 8; nt++) {
            tm0 = fmaxf(tm0, fmaxf(p[nt][0], p[nt][1]));
            tm1 = fmaxf(tm1, fmaxf(p[nt][2], p[nt][3]));
        }
        tm0 = fmaxf(tm0, __shfl_xor_sync(0xffffffffu, tm0, 1));
        tm0 = fmaxf(tm0, __shfl_xor_sync(0xffffffffu, tm0, 2));
        tm1 = fmaxf(tm1, __shfl_xor_sync(0xffffffffu, tm1, 1));
        tm1 = fmaxf(tm1, __shfl_xor_sync(0xffffffffu, tm1, 2));

        float m0 = fmaxf(mrow[0], tm0);
        float m1 = fmaxf(mrow[1], tm1);
        float f0 = __expf(mrow[0] - m0);
        float f1 = __expf(mrow[1] - m1);
        float rs0 = 0.f, rs1 = 0.f;
#pragma unroll
        for (int nt = 0; nt < 8; nt++) {
            p[nt][0] = __expf(p[nt][0] - m0);
            p[nt][1] = __expf(p[nt][1] - m0);
            p[nt][2] = __expf(p[nt][2] - m1);
            p[nt][3] = __expf(p[nt][3] - m1);
            rs0 += p[nt][0] + p[nt][1];
            rs1 += p[nt][2] + p[nt][3];
        }
        rs0 += __shfl_xor_sync(0xffffffffu, rs0, 1);
        rs0 += __shfl_xor_sync(0xffffffffu, rs0, 2);
        rs1 += __shfl_xor_sync(0xffffffffu, rs1, 1);
        rs1 += __shfl_xor_sync(0xffffffffu, rs1, 2);
        lsum[0] = lsum[0] * f0 + rs0;
        lsum[1] = lsum[1] * f1 + rs1;
        mrow[0] = m0;
        mrow[1] = m1;
#pragma unroll
        for (int nt = 0; nt < 16; nt++) {
            oAcc[nt][0] *= f0;
            oAcc[nt][1] *= f0;
            oAcc[nt][2] *= f1;
            oAcc[nt][3] *= f1;
        }

        // ---- O += P V (P hi/lo split from regs, V via ldmatrix.trans) ----
#pragma unroll
        for (int pk = 0; pk < 4; pk++) {
            uint32_t ah[4], al[4];
            {
                const float* pa = p[2 * pk];
                const float* pb = p[2 * pk + 1];
                __nv_bfloat16 ha0 = __float2bfloat16(pa[0]), ha1 = __float2bfloat16(pa[1]);
                __nv_bfloat16 ha2 = __float2bfloat16(pa[2]), ha3 = __float2bfloat16(pa[3]);
                __nv_bfloat16 hb0 = __float2bfloat16(pb[0]), hb1 = __float2bfloat16(pb[1]);
                __nv_bfloat16 hb2 = __float2bfloat16(pb[2]), hb3 = __float2bfloat16(pb[3]);
                ah[0] = pk2(ha0, ha1);
                ah[1] = pk2(ha2, ha3);
                ah[2] = pk2(hb0, hb1);
                ah[3] = pk2(hb2, hb3);
                al[0] = pk2(__float2bfloat16(pa[0] - __bfloat162float(ha0)),
                            __float2bfloat16(pa[1] - __bfloat162float(ha1)));
                al[1] = pk2(__float2bfloat16(pa[2] - __bfloat162float(ha2)),
                            __float2bfloat16(pa[3] - __bfloat162float(ha3)));
                al[2] = pk2(__float2bfloat16(pb[0] - __bfloat162float(hb0)),
                            __float2bfloat16(pb[1] - __bfloat162float(hb1)));
                al[3] = pk2(__float2bfloat16(pb[2] - __bfloat162float(hb2)),
                            __float2bfloat16(pb[3] - __bfloat162float(hb3)));
            }
            const uint32_t vRow = (uint32_t)((pk * 16 + (lid & 15)) * AS) * 2;
#pragma unroll
            for (int nt = 0; nt < 16; nt++) {
                uint32_t bh[2], bl[2];
                ldsm_x2t(bh[0], bh[1], uVh + vRow + nt * 16);
                ldsm_x2t(bl[0], bl[1], uVl + vRow + nt * 16);
                mma_bf16(oAcc[nt], ah, bh);
                mma_bf16(oAcc[nt], ah, bl);
                mma_bf16(oAcc[nt], al, bh);
            }
        }
    }

    // ---- epilogue: normalize, split to bf16 hi/lo, store ----
    const float inv0 = 1.f / lsum[0];
    const float inv1 = 1.f / lsum[1];
    const int col = (lid & 3) * 2;
#pragma unroll
    for (int nt = 0; nt < 16; nt++) {
        float v0 = oAcc[nt][0] * inv0;
        float v1 = oAcc[nt][1] * inv0;
        float v2 = oAcc[nt][2] * inv1;
        float v3 = oAcc[nt][3] * inv1;
        __nv_bfloat16 h0 = __float2bfloat16(v0), h1 = __float2bfloat16(v1);
        __nv_bfloat16 h2 = __float2bfloat16(v2), h3 = __float2bfloat16(v3);
        size_t o0 = (size_t)row0g * HID + hoff + nt * 8 + col;
        size_t o1 = (size_t)row1g * HID + hoff + nt * 8 + col;
        *(uint32_t*)&Oh[o0] = pk2(h0, h1);
        *(uint32_t*)&Ol[o0] = pk2(__float2bfloat16(v0 - __bfloat162float(h0)),
                                  __float2bfloat16(v1 - __bfloat162float(h1)));
        *(uint32_t*)&Oh[o1] = pk2(h2, h3);
        *(uint32_t*)&Ol[o1] = pk2(__float2bfloat16(v2 - __bfloat162float(h2)),
                                  __float2bfloat16(v3 - __bfloat162float(h3)));
    }
}

// ======================= launch =======================
extern "C" void kernel_launch(void* const* d_in, const int* in_sizes, int n_in,
                              void* d_out, int out_size)
{
    const float* X  = (const float*)d_in[0];
    const float* Wq = (const float*)d_in[1];
    const float* Wk = (const float*)d_in[2];
    const float* Wv = (const float*)d_in[3];
    const float* Wo = (const float*)d_in[4];
    float* out = (float*)d_out;

    __nv_bfloat16 *xh, *xl, *qh, *ql, *kh, *kl, *vh, *vl, *oh, *ol;
    cudaGetSymbolAddress((void**)&xh, g_Xh);
    cudaGetSymbolAddress((void**)&xl, g_Xl);
    cudaGetSymbolAddress((void**)&qh, g_Qh);
    cudaGetSymbolAddress((void**)&ql, g_Ql);
    cudaGetSymbolAddress((void**)&kh, g_Kh);
    cudaGetSymbolAddress((void**)&kl, g_Kl);
    cudaGetSymbolAddress((void**)&vh, g_Vh);
    cudaGetSymbolAddress((void**)&vl, g_Vl);
    cudaGetSymbolAddress((void**)&oh, g_Oh);
    cudaGetSymbolAddress((void**)&ol, g_Ol);
    __nv_bfloat16 *wqh, *wql, *wkh, *wkl, *wvh, *wvl, *woh, *wol;
    cudaGetSymbolAddress((void**)&wqh, g_Wqh);
    cudaGetSymbolAddress((void**)&wql, g_Wql);
    cudaGetSymbolAddress((void**)&wkh, g_Wkh);
    cudaGetSymbolAddress((void**)&wkl, g_Wkl);
    cudaGetSymbolAddress((void**)&wvh, g_Wvh);
    cudaGetSymbolAddress((void**)&wvl, g_Wvl);
    cudaGetSymbolAddress((void**)&woh, g_Woh);
    cudaGetSymbolAddress((void**)&wol, g_Wol);

    cudaFuncSetAttribute(gemm_mma,
                         cudaFuncAttributeMaxDynamicSharedMemorySize, GEMM_SMEM);
    cudaFuncSetAttribute(attn_mma,
                         cudaFuncAttributeMaxDynamicSharedMemorySize, ATTN_SMEM);

    const int n4 = SEQ * HID / 4;
    split_kernel<<<(n4 + 255) / 256, 256>>>(X, xh, xl, n4);
    dim3 tG(HID / 32, HID / 32, 4);
    dim3 tB(32, 8);
    tsplit4_kernel<<<tG, tB>>>(Wq, Wk, Wv, Wo,
                               wqh, wql, wkh, wkl, wvh, wvl, woh, wol);

    dim3 gG(HID / 128, SEQ / 128);   // (16, 32) = 512 CTAs
    gemm_mma<<<gG, 256, GEMM_SMEM>>>(xh, xl, wqh, wql, nullptr, qh, ql,
                                     SEQ, HID, HID, SCALE, 1);
    gemm_mma<<<gG, 256, GEMM_SMEM>>>(xh, xl, wkh, wkl, nullptr, kh, kl,
                                     SEQ, HID, HID, 1.0f, 1);
    gemm_mma<<<gG, 256, GEMM_SMEM>>>(xh, xl, wvh, wvl, nullptr, vh, vl,
                                     SEQ, HID, HID, 1.0f, 1);

    attn_mma<<<dim3(SEQ / 128, NHEADS), 256, ATTN_SMEM>>>(qh, ql, kh, kl, vh, vl, oh, ol);

    gemm_mma<<<gG, 256, GEMM_SMEM>>>(oh, ol, woh, wol, out, nullptr, nullptr,
                                     SEQ, HID, HID, 1.0f, 0);
}

// round 16
// speedup vs baseline: 1.8126x; 1.5841x over previous
#include <cuda_runtime.h>
#include <cuda_fp16.h>
#include <cstdint>
#include <math.h>

#define SEQ     4096
#define HID     2048
#define NHEADS  16
#define HDIM    128
#define NGLOB   16
#define HALFWIN 256
#define SCALE   0.08838834764831845f   // 128^-0.5

// ---------------- scratch (static device arrays) ----------------
__device__ __half g_X16[SEQ * HID];
__device__ __half g_Q16[SEQ * HID];
__device__ __half g_K16[SEQ * HID];
__device__ __half g_V16[SEQ * HID];
__device__ __half g_O16[SEQ * HID];
__device__ __half g_Wqh[HID * HID], g_Wql[HID * HID];
__device__ __half g_Wkh[HID * HID], g_Wkl[HID * HID];
__device__ __half g_Wvh[HID * HID], g_Wvl[HID * HID];
__device__ __half g_Woh[HID * HID], g_Wol[HID * HID];

// ---------------- asm helpers (compute_103-legal) ----------------
__device__ __forceinline__ uint32_t smem_u32(const void* p) {
    uint32_t a;
    asm("{ .reg .u64 t; cvta.to.shared.u64 t, %1; cvt.u32.u64 %0, t; }" : "=r"(a) : "l"(p));
    return a;
}
__device__ __forceinline__ void ldsm_x4(uint32_t& r0, uint32_t& r1, uint32_t& r2,
                                        uint32_t& r3, uint32_t addr) {
    asm volatile("ldmatrix.sync.aligned.m8n8.x4.shared.b16 {%0,%1,%2,%3}, [%4];"
                 : "=r"(r0), "=r"(r1), "=r"(r2), "=r"(r3) : "r"(addr));
}
__device__ __forceinline__ void ldsm_x2(uint32_t& r0, uint32_t& r1, uint32_t addr) {
    asm volatile("ldmatrix.sync.aligned.m8n8.x2.shared.b16 {%0,%1}, [%2];"
                 : "=r"(r0), "=r"(r1) : "r"(addr));
}
__device__ __forceinline__ void ldsm_x2t(uint32_t& r0, uint32_t& r1, uint32_t addr) {
    asm volatile("ldmatrix.sync.aligned.m8n8.x2.trans.shared.b16 {%0,%1}, [%2];"
                 : "=r"(r0), "=r"(r1) : "r"(addr));
}
// fp16 MMA: D(f32) += A(f16) * B(f16)
__device__ __forceinline__ void mma_f16(float* c, const uint32_t* a, const uint32_t* b) {
    asm volatile(
        "mma.sync.aligned.m16n8k16.row.col.f32.f16.f16.f32 "
        "{%0,%1,%2,%3}, {%4,%5,%6,%7}, {%8,%9}, {%0,%1,%2,%3};"
        : "+f"(c[0]), "+f"(c[1]), "+f"(c[2]), "+f"(c[3])
        : "r"(a[0]), "r"(a[1]), "r"(a[2]), "r"(a[3]), "r"(b[0]), "r"(b[1]));
}
__device__ __forceinline__ void cp_async16(uint32_t saddr, const void* g) {
    asm volatile("cp.async.cg.shared.global [%0], [%1], 16;" :: "r"(saddr), "l"(g));
}
#define CP_COMMIT() asm volatile("cp.async.commit_group;" ::: "memory")
#define CP_WAIT0()  asm volatile("cp.async.wait_group 0;" ::: "memory")
#define CP_WAIT1()  asm volatile("cp.async.wait_group 1;" ::: "memory")

__device__ __forceinline__ uint32_t pk2h(__half a, __half b) {
    __half2 t = __halves2half2(a, b);   // a -> low half
    return *(uint32_t*)&t;
}

// ---------------- conversion kernels ----------------
// X fp32 -> fp16 (single)
__global__ __launch_bounds__(256) void cvt16_kernel(
    const float* __restrict__ x, __half* __restrict__ o, int n4)
{
    int i = blockIdx.x * blockDim.x + threadIdx.x;
    if (i >= n4) return;
    float4 v = ((const float4*)x)[i];
    ((__half2*)o)[2 * i]     = __floats2half2_rn(v.x, v.y);
    ((__half2*)o)[2 * i + 1] = __floats2half2_rn(v.z, v.w);
}

// 4 weight transposes+splits in one launch: W[K][N] -> Th[N][K], Tl[N][K] (fp16 hi/lo)
__global__ __launch_bounds__(256) void tsplit4_kernel(
    const float* __restrict__ W0, const float* __restrict__ W1,
    const float* __restrict__ W2, const float* __restrict__ W3,
    __half* __restrict__ T0h, __half* __restrict__ T0l,
    __half* __restrict__ T1h, __half* __restrict__ T1l,
    __half* __restrict__ T2h, __half* __restrict__ T2l,
    __half* __restrict__ T3h, __half* __restrict__ T3l)
{
    const float* W;
    __half *Th, *Tl;
    switch (blockIdx.z) {
        case 0: W = W0; Th = T0h; Tl = T0l; break;
        case 1: W = W1; Th = T1h; Tl = T1l; break;
        case 2: W = W2; Th = T2h; Tl = T2l; break;
        default: W = W3; Th = T3h; Tl = T3l; break;
    }
    __shared__ float t[32][33];
    int tx = threadIdx.x, ty = threadIdx.y;
    int bx = blockIdx.x * 32;   // N
    int by = blockIdx.y * 32;   // K
#pragma unroll
    for (int j = 0; j < 32; j += 8)
        t[ty + j][tx] = W[(size_t)(by + ty + j) * HID + bx + tx];
    __syncthreads();
#pragma unroll
    for (int j = 0; j < 32; j += 8) {
        float v = t[tx][ty + j];
        __half hb = __float2half_rn(v);
        float lo = v - __half2float(hb);
        size_t o = (size_t)(bx + ty + j) * HID + by + tx;
        Th[o] = hb;
        Tl[o] = __float2half_rn(lo);
    }
}

// ---------------- HMMA fp16 split-weight GEMM ----------------
// C = alpha * A[M,K](fp16) @ (Bh+Bl)^T  (Bt stored [N][K] K-major, fp16 hi/lo)
// 2 MMAs per tile position (vs 3 with bf16 hi/lo-activations).
// CTA 128x128, BK=32, 8 warps 2x4, warp tile 64x32, reg-capped for 2 CTAs/SM.
#define BKC 32
#define SSTR 40                             // elems per smem row (80 B)
#define GTILE_BY (128 * SSTR * 2)           // 10240 per array tile
#define GSTAGE   (3 * GTILE_BY)             // 30720 (A, Bh, Bl)
#define GEMM_SMEM (2 * GSTAGE)              // 61440  -> 2 CTAs/SM

__global__ __launch_bounds__(256, 2) void gemm_mma(
    const __half* __restrict__ A,
    const __half* __restrict__ Bth, const __half* __restrict__ Btl,
    float* __restrict__ Cf, __half* __restrict__ Ch,
    int M, int N, int K, float alpha, int split_out)
{
    extern __shared__ char dsm[];
    const uint32_t sb = smem_u32(dsm);
    const int tid = threadIdx.x;
    const int wid = tid >> 5;
    const int lid = tid & 31;
    const int row0 = blockIdx.y * 128;
    const int col0 = blockIdx.x * 128;

    // load mapping: 2 threads per 128-row tile row, 16 elems (32B) each
    const int lr = tid >> 1;
    const int ha = (tid & 1) * 16;
    const __half* gA  = A   + (size_t)(row0 + lr) * K + ha;
    const __half* gBh = Bth + (size_t)(col0 + lr) * K + ha;
    const __half* gBl = Btl + (size_t)(col0 + lr) * K + ha;
    const uint32_t so = (uint32_t)(lr * SSTR + ha) * 2;

    const int warpM = (wid >> 2) * 64;
    const int warpN = (wid & 3) * 32;
    const int aRow = warpM + (lid & 15);
    const int aCol = (lid >> 4) * 8;
    const int bRow = warpN + (lid & 7);
    const int bCol = ((lid >> 3) & 1) * 8;

    float acc[4][4][4];
#pragma unroll
    for (int i = 0; i < 4; i++)
#pragma unroll
        for (int j = 0; j < 4; j++)
#pragma unroll
            for (int k = 0; k < 4; k++) acc[i][j][k] = 0.f;

    auto prefetch = [&](int c, int st) {
        const uint32_t base = sb + st * GSTAGE + so;
        const __half* a0 = gA  + c * BKC;
        const __half* b0 = gBh + c * BKC;
        const __half* b1 = gBl + c * BKC;
        cp_async16(base,                a0); cp_async16(base + 16,                a0 + 8);
        cp_async16(base + GTILE_BY,     b0); cp_async16(base + GTILE_BY + 16,     b0 + 8);
        cp_async16(base + 2 * GTILE_BY, b1); cp_async16(base + 2 * GTILE_BY + 16, b1 + 8);
    };

    prefetch(0, 0);
    CP_COMMIT();

    const int nch = K / BKC;
    for (int c = 0; c < nch; c++) {
        CP_WAIT0();
        __syncthreads();
        if (c + 1 < nch) {
            prefetch(c + 1, (c + 1) & 1);
            CP_COMMIT();
        }

        const uint32_t st   = sb + (c & 1) * GSTAGE;
        const uint32_t sAU  = st;
        const uint32_t sBhU = st + GTILE_BY;
        const uint32_t sBlU = st + 2 * GTILE_BY;

#pragma unroll
        for (int ks = 0; ks < 2; ks++) {
            uint32_t bh[4][2], bl[4][2];
            const uint32_t bOff = (uint32_t)(bRow * SSTR + ks * 16 + bCol) * 2;
#pragma unroll
            for (int nt = 0; nt < 4; nt++) {
                ldsm_x2(bh[nt][0], bh[nt][1], sBhU + bOff + nt * 8 * SSTR * 2);
                ldsm_x2(bl[nt][0], bl[nt][1], sBlU + bOff + nt * 8 * SSTR * 2);
            }
            const uint32_t aOff = (uint32_t)(aRow * SSTR + ks * 16 + aCol) * 2;
#pragma unroll
            for (int mt = 0; mt < 4; mt++) {
                uint32_t ah[4];
                ldsm_x4(ah[0], ah[1], ah[2], ah[3], sAU + aOff + mt * 16 * SSTR * 2);
#pragma unroll
                for (int nt = 0; nt < 4; nt++) {
                    mma_f16(acc[mt][nt], ah, bh[nt]);
                    mma_f16(acc[mt][nt], ah, bl[nt]);
                }
            }
        }
    }

    // ---- epilogue ----
    const int qrow = lid >> 2;
    const int qcol = (lid & 3) * 2;
#pragma unroll
    for (int mt = 0; mt < 4; mt++) {
        const int r0g = row0 + warpM + mt * 16 + qrow;
#pragma unroll
        for (int nt = 0; nt < 4; nt++) {
            const int cg = col0 + warpN + nt * 8 + qcol;
            float v0 = alpha * acc[mt][nt][0];
            float v1 = alpha * acc[mt][nt][1];
            float v2 = alpha * acc[mt][nt][2];
            float v3 = alpha * acc[mt][nt][3];
            if (split_out) {
                *(uint32_t*)&Ch[(size_t)r0g * N + cg] =
                    pk2h(__float2half_rn(v0), __float2half_rn(v1));
                *(uint32_t*)&Ch[(size_t)(r0g + 8) * N + cg] =
                    pk2h(__float2half_rn(v2), __float2half_rn(v3));
            } else {
                float2 a0 = {v0, v1}, a1 = {v2, v3};
                *(float2*)&Cf[(size_t)r0g * N + cg]       = a0;
                *(float2*)&Cf[(size_t)(r0g + 8) * N + cg] = a1;
            }
        }
    }
}

// ---------------- fp16 mma.sync flash attention, 3-stage cp.async ----------------
// CTA = (q-block of 128, head), 8 warps (256 thr), warp = 16 q-rows.
// Q/K/V single fp16: QK = 1 MMA, PV = 1 MMA (no hi/lo splits).
#define AS 136                                  // smem row stride (elems)
#define ATILE_B  (64 * AS * 2)                  // 17408 B per array tile (K or V)
#define ASTAGE_B (2 * ATILE_B)                  // 34816 B per stage
#define ATTN_SMEM (3 * ASTAGE_B)                // 104448 B

__global__ __launch_bounds__(256) void attn_mma(
    const __half* __restrict__ Q, const __half* __restrict__ K,
    const __half* __restrict__ V, __half* __restrict__ O)
{
    extern __shared__ char dsm[];
    const uint32_t sb = smem_u32(dsm);

    const int tid = threadIdx.x;
    const int wid = tid >> 5;
    const int lid = tid & 31;
    const int qb = blockIdx.x;
    const int q0 = qb * 128;
    const int h  = blockIdx.y;
    const size_t hoff = (size_t)h * HDIM;

    // ---- stage Q (128 rows fp16) into smem, ldmatrix to regs ----
    {
        const int lr = tid >> 1;               // 0..127
        const int lhalf = (tid & 1) * 64;
        const __half* gq = Q + (size_t)(q0 + lr) * HID + hoff + lhalf;
        __half* sQ = (__half*)dsm;
#pragma unroll
        for (int i = 0; i < 8; i++)
            *(uint4*)&sQ[lr * AS + lhalf + i * 8] = *(const uint4*)(gq + i * 8);
    }
    __syncthreads();
    uint32_t qf[8][4];
    {
        const int aRow = wid * 16 + (lid & 15);
        const int aCol = (lid >> 4) * 8;
#pragma unroll
        for (int kt = 0; kt < 8; kt++) {
            uint32_t ao = (uint32_t)(aRow * AS + kt * 16 + aCol) * 2;
            ldsm_x4(qf[kt][0], qf[kt][1], qf[kt][2], qf[kt][3], sb + ao);
        }
    }
    __syncthreads();   // done with Q staging area before K/V prefetch overwrites it

    // ---- included k-tile list ----
    int tiles[64];
    int ntl = 0;
#pragma unroll 1
    for (int t = 0; t < SEQ / 64; t++) {
        int k0 = t * 64;
        bool inc = (qb == 0) || (t == 0) ||
                   ((k0 + 63 >= q0 - (HALFWIN - 1)) && (k0 <= q0 + 127 + (HALFWIN - 1)));
        if (inc) tiles[ntl++] = t;
    }

    // ---- cp.async prefetch of one K/V tile pair into a stage ----
    const int lr2 = tid >> 2;                  // 0..63 (4 threads per key row)
    const int co  = (tid & 3) * 32;            // elem offset (32 elems = 64B)
    auto prefetch = [&](int t, int st) {
        const size_t gb = (size_t)(t * 64 + lr2) * HID + hoff + co;
        const uint32_t db = sb + st * ASTAGE_B + (uint32_t)(lr2 * AS + co) * 2;
        const __half* gk = K + gb;
        const __half* gv = V + gb;
#pragma unroll
        for (int i = 0; i < 4; i++) {
            cp_async16(db + i * 16,           gk + i * 8);
            cp_async16(db + ATILE_B + i * 16, gv + i * 8);
        }
    };

    prefetch(tiles[0], 0); CP_COMMIT();
    if (ntl > 1) { prefetch(tiles[1], 1); CP_COMMIT(); }

    float oAcc[16][4];
#pragma unroll
    for (int i = 0; i < 16; i++)
#pragma unroll
        for (int j = 0; j < 4; j++) oAcc[i][j] = 0.f;
    float mrow[2] = {-1e30f, -1e30f};
    float lsum[2] = {0.f, 0.f};

    const int row0g = q0 + wid * 16 + (lid >> 2);
    const int row1g = row0g + 8;

#pragma unroll 1
    for (int it = 0; it < ntl; it++) {
        const int t  = tiles[it];
        const int k0 = t * 64;

        if (it == ntl - 1) { CP_WAIT0(); } else { CP_WAIT1(); }
        __syncthreads();
        if (it + 2 < ntl) {
            prefetch(tiles[it + 2], (it + 2) % 3);
            CP_COMMIT();
        }

        const uint32_t st = sb + (it % 3) * ASTAGE_B;
        const uint32_t uK = st;
        const uint32_t uV = st + ATILE_B;

        // ---- S = Q K^T (single fp16 MMA) ----
        float p[8][4];
#pragma unroll
        for (int i = 0; i < 8; i++)
#pragma unroll
            for (int j = 0; j < 4; j++) p[i][j] = 0.f;

#pragma unroll
        for (int kt = 0; kt < 8; kt++) {
            const uint32_t bOff = (uint32_t)((lid & 7) * AS + kt * 16 + ((lid >> 3) & 1) * 8) * 2;
#pragma unroll
            for (int nt = 0; nt < 8; nt++) {
                uint32_t kb[2];
                ldsm_x2(kb[0], kb[1], uK + bOff + nt * 8 * AS * 2);
                mma_f16(p[nt], qf[kt], kb);
            }
        }

        // ---- mask (edge tiles only). full if every |q-k| < HALFWIN ----
        bool fullTile = (k0 >= q0 - 128) && (k0 <= q0 + 192);
        if (!fullTile) {
            const int cb = k0 + 2 * (lid & 3);
#pragma unroll
            for (int nt = 0; nt < 8; nt++) {
                int kg0 = cb + nt * 8, kg1 = kg0 + 1;
                if (!((row0g < NGLOB) | (kg0 < NGLOB) | (abs(row0g - kg0) < HALFWIN))) p[nt][0] = -1e30f;
                if (!((row0g < NGLOB) | (kg1 < NGLOB) | (abs(row0g - kg1) < HALFWIN))) p[nt][1] = -1e30f;
                if (!((row1g < NGLOB) | (kg0 < NGLOB) | (abs(row1g - kg0) < HALFWIN))) p[nt][2] = -1e30f;
                if (!((row1g < NGLOB) | (kg1 < NGLOB) | (abs(row1g - kg1) < HALFWIN))) p[nt][3] = -1e30f;
            }
        }

        // ---- online softmax ----
        float tm0 = -1e30f, tm1 = -1e30f;
#pragma unroll
        for (int nt = 0; nt < 8; nt++) {
            tm0 = fmaxf(tm0, fmaxf(p[nt][0], p[nt][1]));
            tm1 = fmaxf(tm1, fmaxf(p[nt][2], p[nt][3]));
        }
        tm0 = fmaxf(tm0, __shfl_xor_sync(0xffffffffu, tm0, 1));
        tm0 = fmaxf(tm0, __shfl_xor_sync(0xffffffffu, tm0, 2));
        tm1 = fmaxf(tm1, __shfl_xor_sync(0xffffffffu, tm1, 1));
        tm1 = fmaxf(tm1, __shfl_xor_sync(0xffffffffu, tm1, 2));

        float m0 = fmaxf(mrow[0], tm0);
        float m1 = fmaxf(mrow[1], tm1);
        float f0 = __expf(mrow[0] - m0);
        float f1 = __expf(mrow[1] - m1);
        float rs0 = 0.f, rs1 = 0.f;
#pragma unroll
        for (int nt = 0; nt < 8; nt++) {
            p[nt][0] = __expf(p[nt][0] - m0);
            p[nt][1] = __expf(p[nt][1] - m0);
            p[nt][2] = __expf(p[nt][2] - m1);
            p[nt][3] = __expf(p[nt][3] - m1);
            rs0 += p[nt][0] + p[nt][1];
            rs1 += p[nt][2] + p[nt][3];
        }
        rs0 += __shfl_xor_sync(0xffffffffu, rs0, 1);
        rs0 += __shfl_xor_sync(0xffffffffu, rs0, 2);
        rs1 += __shfl_xor_sync(0xffffffffu, rs1, 1);
        rs1 += __shfl_xor_sync(0xffffffffu, rs1, 2);
        lsum[0] = lsum[0] * f0 + rs0;
        lsum[1] = lsum[1] * f1 + rs1;
        mrow[0] = m0;
        mrow[1] = m1;
#pragma unroll
        for (int nt = 0; nt < 16; nt++) {
            oAcc[nt][0] *= f0;
            oAcc[nt][1] *= f0;
            oAcc[nt][2] *= f1;
            oAcc[nt][3] *= f1;
        }

        // ---- O += P V (P packed to fp16 from regs, V via ldmatrix.trans) ----
#pragma unroll
        for (int pk = 0; pk < 4; pk++) {
            uint32_t ah[4];
            {
                const float* pa = p[2 * pk];
                const float* pb = p[2 * pk + 1];
                ah[0] = pk2h(__float2half_rn(pa[0]), __float2half_rn(pa[1]));
                ah[1] = pk2h(__float2half_rn(pa[2]), __float2half_rn(pa[3]));
                ah[2] = pk2h(__float2half_rn(pb[0]), __float2half_rn(pb[1]));
                ah[3] = pk2h(__float2half_rn(pb[2]), __float2half_rn(pb[3]));
            }
            const uint32_t vRow = (uint32_t)((pk * 16 + (lid & 15)) * AS) * 2;
#pragma unroll
            for (int nt = 0; nt < 16; nt++) {
                uint32_t vb[2];
                ldsm_x2t(vb[0], vb[1], uV + vRow + nt * 16);
                mma_f16(oAcc[nt], ah, vb);
            }
        }
    }

    // ---- epilogue: normalize, store fp16 ----
    const float inv0 = 1.f / lsum[0];
    const float inv1 = 1.f / lsum[1];
    const int col = (lid & 3) * 2;
#pragma unroll
    for (int nt = 0; nt < 16; nt++) {
        float v0 = oAcc[nt][0] * inv0;
        float v1 = oAcc[nt][1] * inv0;
        float v2 = oAcc[nt][2] * inv1;
        float v3 = oAcc[nt][3] * inv1;
        size_t o0 = (size_t)row0g * HID + hoff + nt * 8 + col;
        size_t o1 = (size_t)row1g * HID + hoff + nt * 8 + col;
        *(uint32_t*)&O[o0] = pk2h(__float2half_rn(v0), __float2half_rn(v1));
        *(uint32_t*)&O[o1] = pk2h(__float2half_rn(v2), __float2half_rn(v3));
    }
}

// ======================= launch =======================
extern "C" void kernel_launch(void* const* d_in, const int* in_sizes, int n_in,
                              void* d_out, int out_size)
{
    const float* X  = (const float*)d_in[0];
    const float* Wq = (const float*)d_in[1];
    const float* Wk = (const float*)d_in[2];
    const float* Wv = (const float*)d_in[3];
    const float* Wo = (const float*)d_in[4];
    float* out = (float*)d_out;

    __half *x16, *q16, *k16, *v16, *o16;
    cudaGetSymbolAddress((void**)&x16, g_X16);
    cudaGetSymbolAddress((void**)&q16, g_Q16);
    cudaGetSymbolAddress((void**)&k16, g_K16);
    cudaGetSymbolAddress((void**)&v16, g_V16);
    cudaGetSymbolAddress((void**)&o16, g_O16);
    __half *wqh, *wql, *wkh, *wkl, *wvh, *wvl, *woh, *wol;
    cudaGetSymbolAddress((void**)&wqh, g_Wqh);
    cudaGetSymbolAddress((void**)&wql, g_Wql);
    cudaGetSymbolAddress((void**)&wkh, g_Wkh);
    cudaGetSymbolAddress((void**)&wkl, g_Wkl);
    cudaGetSymbolAddress((void**)&wvh, g_Wvh);
    cudaGetSymbolAddress((void**)&wvl, g_Wvl);
    cudaGetSymbolAddress((void**)&woh, g_Woh);
    cudaGetSymbolAddress((void**)&wol, g_Wol);

    cudaFuncSetAttribute(gemm_mma,
                         cudaFuncAttributeMaxDynamicSharedMemorySize, GEMM_SMEM);
    cudaFuncSetAttribute(attn_mma,
                         cudaFuncAttributeMaxDynamicSharedMemorySize, ATTN_SMEM);

    const int n4 = SEQ * HID / 4;
    cvt16_kernel<<<(n4 + 255) / 256, 256>>>(X, x16, n4);
    dim3 tG(HID / 32, HID / 32, 4);
    dim3 tB(32, 8);
    tsplit4_kernel<<<tG, tB>>>(Wq, Wk, Wv, Wo,
                               wqh, wql, wkh, wkl, wvh, wvl, woh, wol);

    dim3 gG(HID / 128, SEQ / 128);   // (16, 32) = 512 CTAs
    gemm_mma<<<gG, 256, GEMM_SMEM>>>(x16, wqh, wql, nullptr, q16,
                                     SEQ, HID, HID, SCALE, 1);
    gemm_mma<<<gG, 256, GEMM_SMEM>>>(x16, wkh, wkl, nullptr, k16,
                                     SEQ, HID, HID, 1.0f, 1);
    gemm_mma<<<gG, 256, GEMM_SMEM>>>(x16, wvh, wvl, nullptr, v16,
                                     SEQ, HID, HID, 1.0f, 1);

    attn_mma<<<dim3(SEQ / 128, NHEADS), 256, ATTN_SMEM>>>(q16, k16, v16, o16);

    gemm_mma<<<gG, 256, GEMM_SMEM>>>(o16, woh, wol, out, nullptr,
                                     SEQ, HID, HID, 1.0f, 0);
}